// round 2
// baseline (speedup 1.0000x reference)
#include <cuda_runtime.h>
#include <math.h>

#define BATCH 4
#define SEQ   4096
#define HID   1024
#define FF    4096
#define NROWS (BATCH*SEQ)          // 16384
#define TOT   (NROWS*HID)          // 16777216

// ---------------- scratch (static device arrays; no allocation allowed) ----
__device__ float  g_fr[TOT];               // hidden-FFT real / later: x_ft real
__device__ float  g_fi[TOT];               // hidden-FFT imag / later: y = h+ffn
__device__ float  g_h [TOT];               // h = LN1(x + x_ft)
__device__ float  g_act[NROWS*FF];         // gelu(h@w1+b1), 256 MB
__device__ float2 g_tw[2048];              // e^{-2*pi*i*j/4096}, j=0..2047

// ---------------- twiddle init ---------------------------------------------
__global__ void twiddle_init_kernel() {
    int j = blockIdx.x * blockDim.x + threadIdx.x;
    if (j < 2048) {
        float ang = -6.283185307179586f * (float)j / 4096.0f;
        float s, c;
        sincosf(ang, &s, &c);
        g_tw[j] = make_float2(c, s);
    }
}

// ---------------- FFT over hidden dim (N=1024), one row per block ----------
__global__ void fft_hidden_kernel(const float* __restrict__ x) {
    __shared__ float sr[1024];
    __shared__ float si[1024];
    const int row = blockIdx.x;                 // b*SEQ + s
    const float* xp = x + (size_t)row * HID;

    // bit-reversed load (real input)
    for (int i = threadIdx.x; i < 1024; i += 256) {
        int r = __brev((unsigned)i) >> 22;      // 10-bit reversal
        sr[r] = xp[i];
        si[r] = 0.f;
    }
    __syncthreads();

    #pragma unroll
    for (int s = 1; s <= 10; s++) {
        const int half = 1 << (s - 1);
        for (int j = threadIdx.x; j < 512; j += 256) {
            int k  = j & (half - 1);
            int i0 = ((j >> (s - 1)) << s) + k;
            int i1 = i0 + half;
            // twiddle e^{-2pi i k / 2^s} = g_tw[k << (12 - s)]
            float2 w = g_tw[k << (12 - s)];
            float xr = sr[i1], xi = si[i1];
            float tr = w.x * xr - w.y * xi;
            float ti = w.y * xr + w.x * xi;
            sr[i1] = sr[i0] - tr; si[i1] = si[i0] - ti;
            sr[i0] += tr;          si[i0] += ti;
        }
        __syncthreads();
    }

    float* fr = g_fr + (size_t)row * HID;
    float* fi = g_fi + (size_t)row * HID;
    for (int i = threadIdx.x; i < 1024; i += 256) {
        fr[i] = sr[i];
        fi[i] = si[i];
    }
}

// ---------------- FFT over seq dim (N=4096), one (b,h) column per block ----
// Reads complex column from g_fr/g_fi, writes REAL part back into g_fr.
__global__ void fft_seq_kernel() {
    __shared__ float sr[4096];
    __shared__ float si[4096];
    const int col = blockIdx.x;                 // b*HID + h
    const int b   = col >> 10;
    const int h   = col & 1023;
    const size_t base = (size_t)b * SEQ * HID + h;

    for (int i = threadIdx.x; i < 4096; i += blockDim.x) {
        int r = __brev((unsigned)i) >> 20;      // 12-bit reversal
        sr[r] = g_fr[base + (size_t)i * HID];
        si[r] = g_fi[base + (size_t)i * HID];
    }
    __syncthreads();

    #pragma unroll
    for (int s = 1; s <= 12; s++) {
        const int half = 1 << (s - 1);
        for (int j = threadIdx.x; j < 2048; j += blockDim.x) {
            int k  = j & (half - 1);
            int i0 = ((j >> (s - 1)) << s) + k;
            int i1 = i0 + half;
            float2 w = g_tw[k << (12 - s)];
            float xr = sr[i1], xi = si[i1];
            float tr = w.x * xr - w.y * xi;
            float ti = w.y * xr + w.x * xi;
            sr[i1] = sr[i0] - tr; si[i1] = si[i0] - ti;
            sr[i0] += tr;          si[i0] += ti;
        }
        __syncthreads();
    }

    for (int i = threadIdx.x; i < 4096; i += blockDim.x) {
        g_fr[base + (size_t)i * HID] = sr[i];   // real part only
    }
}

// ---------------- out = LayerNorm(a [+ b]) over last dim (1024) ------------
__global__ void add_ln_kernel(const float* __restrict__ a,
                              const float* __restrict__ badd,
                              const float* __restrict__ gamma,
                              const float* __restrict__ beta,
                              float* __restrict__ out) {
    const int row = blockIdx.x;
    const int tid = threadIdx.x;                // 256 threads, 4 floats each
    const float4* a4 = (const float4*)(a + (size_t)row * HID);
    float4 v = a4[tid];
    if (badd) {
        const float4* b4 = (const float4*)(badd + (size_t)row * HID);
        float4 w = b4[tid];
        v.x += w.x; v.y += w.y; v.z += w.z; v.w += w.w;
    }
    float sum = v.x + v.y + v.z + v.w;
    float sq  = v.x*v.x + v.y*v.y + v.z*v.z + v.w*v.w;

    __shared__ float s1[8], s2[8];
    #pragma unroll
    for (int o = 16; o > 0; o >>= 1) {
        sum += __shfl_xor_sync(0xffffffffu, sum, o);
        sq  += __shfl_xor_sync(0xffffffffu, sq,  o);
    }
    const int warp = tid >> 5, lane = tid & 31;
    if (lane == 0) { s1[warp] = sum; s2[warp] = sq; }
    __syncthreads();
    if (warp == 0) {
        float a1 = (lane < 8) ? s1[lane] : 0.f;
        float a2 = (lane < 8) ? s2[lane] : 0.f;
        #pragma unroll
        for (int o = 4; o > 0; o >>= 1) {
            a1 += __shfl_xor_sync(0xffffffffu, a1, o);
            a2 += __shfl_xor_sync(0xffffffffu, a2, o);
        }
        if (lane == 0) { s1[0] = a1; s2[0] = a2; }
    }
    __syncthreads();

    const float mu  = s1[0] * (1.0f / 1024.0f);
    const float var = s2[0] * (1.0f / 1024.0f) - mu * mu;
    const float inv = rsqrtf(var + 1e-5f);

    const float4 g  = ((const float4*)gamma)[tid];
    const float4 bt = ((const float4*)beta)[tid];
    float4 o;
    o.x = (v.x - mu) * inv * g.x + bt.x;
    o.y = (v.y - mu) * inv * g.y + bt.y;
    o.z = (v.z - mu) * inv * g.z + bt.z;
    o.w = (v.w - mu) * inv * g.w + bt.w;
    ((float4*)(out + (size_t)row * HID))[tid] = o;
}

// ---------------- fp32 SGEMM, 128x128 tile, 8x8/thread, BK=8 ---------------
// mode 0: C = gelu_exact(A@B + bias)
// mode 1: C = A@B + bias + res
__global__ void __launch_bounds__(256)
sgemm_kernel(const float* __restrict__ A, const float* __restrict__ Bm,
             const float* __restrict__ bias, const float* __restrict__ res,
             float* __restrict__ C, int M, int N, int K, int mode) {
    __shared__ float As[8][128];
    __shared__ float Bs[8][128];

    const int tid = threadIdx.x;
    const int m0 = blockIdx.y * 128;
    const int n0 = blockIdx.x * 128;

    const int aRow = tid >> 1;                  // 0..127
    const int aCol = (tid & 1) * 4;             // 0 or 4
    const int bRow = tid >> 5;                  // 0..7
    const int bCol = (tid & 31) * 4;            // 0..124
    const int ty = tid >> 4, tx = tid & 15;
    const int ry = ty * 8,  cx = tx * 8;

    float acc[8][8];
    #pragma unroll
    for (int i = 0; i < 8; i++)
        #pragma unroll
        for (int j = 0; j < 8; j++) acc[i][j] = 0.f;

    const float* Aptr = A  + (size_t)(m0 + aRow) * K + aCol;
    const float* Bptr = Bm + (size_t)bRow * N + (n0 + bCol);

    for (int k0 = 0; k0 < K; k0 += 8) {
        float4 av = *(const float4*)(Aptr + k0);
        float4 bv = *(const float4*)(Bptr + (size_t)k0 * N);
        As[aCol + 0][aRow] = av.x;
        As[aCol + 1][aRow] = av.y;
        As[aCol + 2][aRow] = av.z;
        As[aCol + 3][aRow] = av.w;
        *(float4*)&Bs[bRow][bCol] = bv;
        __syncthreads();

        #pragma unroll
        for (int kk = 0; kk < 8; kk++) {
            float a[8], bb[8];
            *(float4*)&a[0]  = *(const float4*)&As[kk][ry];
            *(float4*)&a[4]  = *(const float4*)&As[kk][ry + 4];
            *(float4*)&bb[0] = *(const float4*)&Bs[kk][cx];
            *(float4*)&bb[4] = *(const float4*)&Bs[kk][cx + 4];
            #pragma unroll
            for (int i = 0; i < 8; i++)
                #pragma unroll
                for (int j = 0; j < 8; j++)
                    acc[i][j] = fmaf(a[i], bb[j], acc[i][j]);
        }
        __syncthreads();
    }

    // epilogue
    float bv[8];
    #pragma unroll
    for (int j = 0; j < 8; j++) bv[j] = bias[n0 + cx + j];

    #pragma unroll
    for (int i = 0; i < 8; i++) {
        const size_t rbase = (size_t)(m0 + ry + i) * N + (n0 + cx);
        float* crow = C + rbase;
        float o[8];
        if (mode == 0) {
            #pragma unroll
            for (int j = 0; j < 8; j++) {
                float v = acc[i][j] + bv[j];
                o[j] = 0.5f * v * (1.0f + erff(v * 0.70710678118654752f));
            }
        } else {
            const float* rrow = res + rbase;
            #pragma unroll
            for (int j = 0; j < 8; j++) {
                o[j] = acc[i][j] + bv[j] + rrow[j];
            }
        }
        *(float4*)&crow[0] = make_float4(o[0], o[1], o[2], o[3]);
        *(float4*)&crow[4] = make_float4(o[4], o[5], o[6], o[7]);
    }
}

// ---------------- launch ----------------------------------------------------
extern "C" void kernel_launch(void* const* d_in, const int* in_sizes, int n_in,
                              void* d_out, int out_size) {
    const float* x   = (const float*)d_in[0];
    const float* w1  = (const float*)d_in[1];
    const float* b1  = (const float*)d_in[2];
    const float* w2  = (const float*)d_in[3];
    const float* b2  = (const float*)d_in[4];
    const float* g1  = (const float*)d_in[5];
    const float* be1 = (const float*)d_in[6];
    const float* g2  = (const float*)d_in[7];
    const float* be2 = (const float*)d_in[8];
    float* out = (float*)d_out;

    float *fr, *fi, *h, *act;
    cudaGetSymbolAddress((void**)&fr,  g_fr);
    cudaGetSymbolAddress((void**)&fi,  g_fi);
    cudaGetSymbolAddress((void**)&h,   g_h);
    cudaGetSymbolAddress((void**)&act, g_act);

    // 1. twiddle table
    twiddle_init_kernel<<<8, 256>>>();
    // 2. FFT over hidden dim -> (g_fr, g_fi)
    fft_hidden_kernel<<<NROWS, 256>>>(x);
    // 3. FFT over seq dim, real part -> g_fr  (= x_ft)
    fft_seq_kernel<<<BATCH * HID, 512>>>();
    // 4. h = LN1(x + x_ft)
    add_ln_kernel<<<NROWS, 256>>>(x, fr, g1, be1, h);
    // 5. act = gelu(h @ w1 + b1)    [16384x1024 @ 1024x4096]
    sgemm_kernel<<<dim3(FF / 128, NROWS / 128), 256>>>(
        h, w1, b1, nullptr, act, NROWS, FF, HID, 0);
    // 6. y = act @ w2 + b2 + h -> g_fi   [16384x4096 @ 4096x1024]
    sgemm_kernel<<<dim3(HID / 128, NROWS / 128), 256>>>(
        act, w2, b2, h, fi, NROWS, HID, FF, 1);
    // 7. out = LN2(y)
    add_ln_kernel<<<NROWS, 256>>>(fi, nullptr, g2, be2, out);
}

// round 7
// speedup vs baseline: 2.3371x; 2.3371x over previous
#include <cuda_runtime.h>
#include <cuda_bf16.h>
#include <math.h>
#include <stdint.h>

#define BATCH 4
#define SEQ   4096
#define HID   1024
#define FF    4096
#define NROWS (BATCH*SEQ)          // 16384
#define TOT   (NROWS*HID)          // 16777216

// ---------------- scratch (static device arrays; no allocation allowed) ----
__device__ float  g_fr[TOT];                 // x_ft; later reused: h hi/lo bf16
__device__ float  g_fi[TOT];                 // hidden-FFT imag; later: y
__device__ float  g_h [TOT];                 // h = LN1(x + x_ft)
__device__ __nv_bfloat16 g_act_hi[(size_t)NROWS*FF];
__device__ __nv_bfloat16 g_act_lo[(size_t)NROWS*FF];
__device__ __nv_bfloat16 g_w1t_hi[(size_t)HID*FF];  // [FF][HID] K-major
__device__ __nv_bfloat16 g_w1t_lo[(size_t)HID*FF];
__device__ __nv_bfloat16 g_w2t_hi[(size_t)HID*FF];  // [HID][FF] K-major
__device__ __nv_bfloat16 g_w2t_lo[(size_t)HID*FF];
__device__ float2 g_tw[2048];                // e^{-2*pi*i*j/4096}

// ============================================================================
// PTX helpers (arch-generic only: mma.sync + cp.async)
// ============================================================================
__device__ __forceinline__ uint32_t smem_u32(const void* p) {
    uint32_t a;
    asm("{ .reg .u64 t; cvta.to.shared.u64 t, %1; cvt.u32.u64 %0, t; }"
        : "=r"(a) : "l"(p));
    return a;
}
__device__ __forceinline__ void mma16816(float* d,
                                         uint32_t a0, uint32_t a1, uint32_t a2, uint32_t a3,
                                         uint32_t b0, uint32_t b1) {
    asm volatile(
        "mma.sync.aligned.m16n8k16.row.col.f32.bf16.bf16.f32 "
        "{%0,%1,%2,%3}, {%4,%5,%6,%7}, {%8,%9}, {%0,%1,%2,%3};"
        : "+f"(d[0]), "+f"(d[1]), "+f"(d[2]), "+f"(d[3])
        : "r"(a0), "r"(a1), "r"(a2), "r"(a3), "r"(b0), "r"(b1));
}
#define CP_ASYNC16(dst_u32, src_ptr) \
    asm volatile("cp.async.cg.shared.global [%0], [%1], 16;" \
        :: "r"(dst_u32), "l"(src_ptr))
#define CP_COMMIT() asm volatile("cp.async.commit_group;" ::: "memory")
#define CP_WAIT(n)  asm volatile("cp.async.wait_group %0;" :: "n"(n) : "memory")

// ---------------- twiddle init ---------------------------------------------
__global__ void twiddle_init_kernel() {
    int j = blockIdx.x * blockDim.x + threadIdx.x;
    if (j < 2048) {
        float ang = -6.283185307179586f * (float)j / 4096.0f;
        float s, c;
        sincosf(ang, &s, &c);
        g_tw[j] = make_float2(c, s);
    }
}

// ---------------- weight transpose + hi/lo split ----------------------------
// W: [K][N] fp32 row-major  ->  Thi/Tlo: [N][K] bf16 row-major (K-major operand)
__global__ void transpose_split_kernel(const float* __restrict__ W,
                                       __nv_bfloat16* __restrict__ Thi,
                                       __nv_bfloat16* __restrict__ Tlo,
                                       int K, int N) {
    __shared__ float t[32][33];
    const int n = blockIdx.x * 32 + threadIdx.x;
    const int k0 = blockIdx.y * 32;
    #pragma unroll
    for (int j = 0; j < 32; j += 8)
        t[threadIdx.y + j][threadIdx.x] = W[(size_t)(k0 + threadIdx.y + j) * N + n];
    __syncthreads();
    const int k = k0 + threadIdx.x;
    #pragma unroll
    for (int j = 0; j < 32; j += 8) {
        float v = t[threadIdx.x][threadIdx.y + j];
        __nv_bfloat16 hi = __float2bfloat16(v);
        float lo = v - __bfloat162float(hi);
        size_t o = (size_t)(blockIdx.x * 32 + threadIdx.y + j) * K + k;
        Thi[o] = hi;
        Tlo[o] = __float2bfloat16(lo);
    }
}

// ---------------- fp32 -> bf16 hi/lo split (elementwise) --------------------
__global__ void split_kernel(const float* __restrict__ src,
                             __nv_bfloat16* __restrict__ hi,
                             __nv_bfloat16* __restrict__ lo) {
    const size_t i = ((size_t)blockIdx.x * blockDim.x + threadIdx.x) * 4;
    float4 v = *(const float4*)(src + i);
    __nv_bfloat16 h[4], l[4];
    float vv[4] = {v.x, v.y, v.z, v.w};
    #pragma unroll
    for (int e = 0; e < 4; e++) {
        h[e] = __float2bfloat16(vv[e]);
        l[e] = __float2bfloat16(vv[e] - __bfloat162float(h[e]));
    }
    *(uint2*)(hi + i) = *(uint2*)h;
    *(uint2*)(lo + i) = *(uint2*)l;
}

// ---------------- FFT over hidden dim (N=1024), one row per block ----------
#define SWB10(i) ((i) ^ (((i) >> 5) & 31))
__global__ void fft_hidden_kernel(const float* __restrict__ x) {
    __shared__ float2 sc[1024];
    const int row = blockIdx.x;
    const float* xp = x + (size_t)row * HID;
    for (int i = threadIdx.x; i < 1024; i += 256) {
        int r = __brev((unsigned)i) >> 22;
        sc[SWB10(r)] = make_float2(xp[i], 0.f);
    }
    __syncthreads();
    #pragma unroll
    for (int s = 1; s <= 10; s++) {
        const int half = 1 << (s - 1);
        for (int j = threadIdx.x; j < 512; j += 256) {
            int k  = j & (half - 1);
            int i0 = ((j >> (s - 1)) << s) + k;
            int i1 = i0 + half;
            float2 w = g_tw[k << (12 - s)];
            float2 a = sc[SWB10(i0)];
            float2 b = sc[SWB10(i1)];
            float tr = w.x * b.x - w.y * b.y;
            float ti = w.y * b.x + w.x * b.y;
            sc[SWB10(i1)] = make_float2(a.x - tr, a.y - ti);
            sc[SWB10(i0)] = make_float2(a.x + tr, a.y + ti);
        }
        __syncthreads();
    }
    float* fr = g_fr + (size_t)row * HID;
    float* fi = g_fi + (size_t)row * HID;
    for (int i = threadIdx.x; i < 1024; i += 256) {
        float2 v = sc[SWB10(i)];
        fr[i] = v.x;
        fi[i] = v.y;
    }
}

// ---------------- FFT over seq dim (N=4096), FOUR (b,h) columns per block --
#define SWB12(i) ((i) ^ (((i) >> 7) & 31))
#define SEQ_SMEM (4 * 4096 * (int)sizeof(float2))   // 128 KB
__global__ void fft_seq_kernel() {
    extern __shared__ float2 sc4[];                 // [4][4096]
    const int col0 = blockIdx.x * 4;                // groups never straddle b
    const int b    = col0 >> 10;
    const int h0   = col0 & 1023;
    const size_t base = (size_t)b * SEQ * HID + h0;

    for (int i = threadIdx.x; i < 4096; i += 512) {
        int r = SWB12(__brev((unsigned)i) >> 20);
        float4 vr = *(const float4*)(g_fr + base + (size_t)i * HID);
        float4 vi = *(const float4*)(g_fi + base + (size_t)i * HID);
        sc4[0 * 4096 + r] = make_float2(vr.x, vi.x);
        sc4[1 * 4096 + r] = make_float2(vr.y, vi.y);
        sc4[2 * 4096 + r] = make_float2(vr.z, vi.z);
        sc4[3 * 4096 + r] = make_float2(vr.w, vi.w);
    }
    __syncthreads();

    {
        const int c  = threadIdx.x >> 7;            // 0..3, warp-uniform
        const int jb = threadIdx.x & 127;
        float2* cs = sc4 + c * 4096;
        #pragma unroll
        for (int s = 1; s <= 12; s++) {
            const int half = 1 << (s - 1);
            for (int j = jb; j < 2048; j += 128) {
                int k  = j & (half - 1);
                int i0 = ((j >> (s - 1)) << s) + k;
                int i1 = i0 + half;
                float2 w = g_tw[k << (12 - s)];
                float2 a = cs[SWB12(i0)];
                float2 bb = cs[SWB12(i1)];
                float tr = w.x * bb.x - w.y * bb.y;
                float ti = w.y * bb.x + w.x * bb.y;
                cs[SWB12(i1)] = make_float2(a.x - tr, a.y - ti);
                cs[SWB12(i0)] = make_float2(a.x + tr, a.y + ti);
            }
            __syncthreads();
        }
    }

    for (int i = threadIdx.x; i < 4096; i += 512) {
        int si = SWB12(i);
        float4 o = make_float4(sc4[0 * 4096 + si].x, sc4[1 * 4096 + si].x,
                               sc4[2 * 4096 + si].x, sc4[3 * 4096 + si].x);
        *(float4*)(g_fr + base + (size_t)i * HID) = o;   // real part only
    }
}

// ---------------- out = LayerNorm(a [+ b]) over last dim (1024) ------------
__global__ void add_ln_kernel(const float* __restrict__ a,
                              const float* __restrict__ badd,
                              const float* __restrict__ gamma,
                              const float* __restrict__ beta,
                              float* __restrict__ out) {
    const int row = blockIdx.x;
    const int tid = threadIdx.x;
    const float4* a4 = (const float4*)(a + (size_t)row * HID);
    float4 v = a4[tid];
    if (badd) {
        const float4* b4 = (const float4*)(badd + (size_t)row * HID);
        float4 w = b4[tid];
        v.x += w.x; v.y += w.y; v.z += w.z; v.w += w.w;
    }
    float sum = v.x + v.y + v.z + v.w;
    float sq  = v.x*v.x + v.y*v.y + v.z*v.z + v.w*v.w;
    __shared__ float s1[8], s2[8];
    #pragma unroll
    for (int o = 16; o > 0; o >>= 1) {
        sum += __shfl_xor_sync(0xffffffffu, sum, o);
        sq  += __shfl_xor_sync(0xffffffffu, sq,  o);
    }
    const int warp = tid >> 5, lane = tid & 31;
    if (lane == 0) { s1[warp] = sum; s2[warp] = sq; }
    __syncthreads();
    if (warp == 0) {
        float a1 = (lane < 8) ? s1[lane] : 0.f;
        float a2 = (lane < 8) ? s2[lane] : 0.f;
        #pragma unroll
        for (int o = 4; o > 0; o >>= 1) {
            a1 += __shfl_xor_sync(0xffffffffu, a1, o);
            a2 += __shfl_xor_sync(0xffffffffu, a2, o);
        }
        if (lane == 0) { s1[0] = a1; s2[0] = a2; }
    }
    __syncthreads();
    const float mu  = s1[0] * (1.0f / 1024.0f);
    const float var = s2[0] * (1.0f / 1024.0f) - mu * mu;
    const float inv = rsqrtf(var + 1e-5f);
    const float4 g  = ((const float4*)gamma)[tid];
    const float4 bt = ((const float4*)beta)[tid];
    float4 o;
    o.x = (v.x - mu) * inv * g.x + bt.x;
    o.y = (v.y - mu) * inv * g.y + bt.y;
    o.z = (v.z - mu) * inv * g.z + bt.z;
    o.w = (v.w - mu) * inv * g.w + bt.w;
    ((float4*)(out + (size_t)row * HID))[tid] = o;
}

// ============================================================================
// bf16 split GEMM on mma.sync.m16n8k16 (HMMA).  CTA tile 128x128, BK=32,
// 8 warps (2x4), warp tile 64x32.  cp.async double-buffered smem.
// 3 split terms: Ahi*Bhi + Ahi*Blo + Alo*Bhi into fp32 accumulators.
// GELU=1: C = gelu(A@B + bias) -> bf16 hi/lo.   GELU=0: C = A@B+bias+res (f32)
// ============================================================================
#define LDK 40                      // padded row stride (bf16 elems), 80 bytes
#define BUF_BYTES (128 * LDK * 2)   // 10240 B
#define GEMM_SMEM (8 * BUF_BYTES)   // 2 stages x 4 buffers = 80 KB

template<int GELU>
__global__ void __launch_bounds__(256)
mma_gemm_kernel(const __nv_bfloat16* __restrict__ Ahi,
                const __nv_bfloat16* __restrict__ Alo,
                const __nv_bfloat16* __restrict__ Bhi,
                const __nv_bfloat16* __restrict__ Blo,
                const float* __restrict__ bias,
                const float* __restrict__ res,
                __nv_bfloat16* __restrict__ Ohi,
                __nv_bfloat16* __restrict__ Olo,
                float* __restrict__ Of,
                int M, int N, int K)
{
    extern __shared__ __nv_bfloat16 smem[];   // [2 stages][4 bufs][128][LDK]
    const int tid  = threadIdx.x;
    const int wid  = tid >> 5;
    const int lane = tid & 31;
    const int wm = wid >> 2;        // 0..1
    const int wn = wid & 3;         // 0..3
    const int g  = lane >> 2;       // 0..7
    const int tg = lane & 3;        // 0..3
    const int m0 = blockIdx.y * 128;
    const int n0 = blockIdx.x * 128;

    // cp.async mapping: 2 chunks of 16B per thread per buffer
    const int r0c = tid >> 2;              // rows 0..63
    const int kc0 = (tid & 3) * 8;         // bf16 elem offset within BK=32
    const uint32_t sbase = smem_u32(smem);

    const __nv_bfloat16* srcA[2] = {Ahi, Alo};
    const __nv_bfloat16* srcB[2] = {Bhi, Blo};

    float acc[4][4][4];
    #pragma unroll
    for (int i = 0; i < 4; i++)
        #pragma unroll
        for (int j = 0; j < 4; j++)
            #pragma unroll
            for (int e = 0; e < 4; e++) acc[i][j][e] = 0.f;

    const int NC = K >> 5;          // K / 32

    // ---- prefetch helper (macro to keep cp.async src as plain pointer) ----
    #define PREFETCH(cidx, stage) do {                                         \
        const int _k0 = (cidx) << 5;                                           \
        uint32_t _sb = sbase + (stage) * 4 * BUF_BYTES;                        \
        _Pragma("unroll")                                                      \
        for (int _h = 0; _h < 2; _h++) {                                       \
            _Pragma("unroll")                                                  \
            for (int _half = 0; _half < 2; _half++) {                          \
                int _row = r0c + _half * 64;                                   \
                uint32_t _d = _sb + (_h) * BUF_BYTES +                         \
                              (_row * LDK + kc0) * 2;                          \
                CP_ASYNC16(_d, srcA[_h] + (size_t)(m0 + _row) * K + _k0 + kc0);\
                uint32_t _d2 = _sb + (2 + _h) * BUF_BYTES +                    \
                               (_row * LDK + kc0) * 2;                         \
                CP_ASYNC16(_d2, srcB[_h] + (size_t)(n0 + _row) * K + _k0 + kc0);\
            }                                                                  \
        }                                                                      \
        CP_COMMIT();                                                           \
    } while (0)

    PREFETCH(0, 0);

    for (int c = 0; c < NC; c++) {
        const int st = c & 1;
        if (c + 1 < NC) { PREFETCH(c + 1, st ^ 1); CP_WAIT(1); }
        else            { CP_WAIT(0); }
        __syncthreads();

        const __nv_bfloat16* sAh = smem + (size_t)(st * 4 + 0) * (128 * LDK);
        const __nv_bfloat16* sAl = smem + (size_t)(st * 4 + 1) * (128 * LDK);
        const __nv_bfloat16* sBh = smem + (size_t)(st * 4 + 2) * (128 * LDK);
        const __nv_bfloat16* sBl = smem + (size_t)(st * 4 + 3) * (128 * LDK);

        #pragma unroll
        for (int ks = 0; ks < 2; ks++) {
            const int kk = ks * 16 + tg * 2;
            uint32_t ah[4][4], al[4][4], bh[4][2], bl[4][2];
            #pragma unroll
            for (int mf = 0; mf < 4; mf++) {
                const int r = wm * 64 + mf * 16 + g;
                ah[mf][0] = *(const uint32_t*)&sAh[r * LDK + kk];
                ah[mf][1] = *(const uint32_t*)&sAh[(r + 8) * LDK + kk];
                ah[mf][2] = *(const uint32_t*)&sAh[r * LDK + kk + 8];
                ah[mf][3] = *(const uint32_t*)&sAh[(r + 8) * LDK + kk + 8];
                al[mf][0] = *(const uint32_t*)&sAl[r * LDK + kk];
                al[mf][1] = *(const uint32_t*)&sAl[(r + 8) * LDK + kk];
                al[mf][2] = *(const uint32_t*)&sAl[r * LDK + kk + 8];
                al[mf][3] = *(const uint32_t*)&sAl[(r + 8) * LDK + kk + 8];
            }
            #pragma unroll
            for (int nf = 0; nf < 4; nf++) {
                const int r = wn * 32 + nf * 8 + g;
                bh[nf][0] = *(const uint32_t*)&sBh[r * LDK + kk];
                bh[nf][1] = *(const uint32_t*)&sBh[r * LDK + kk + 8];
                bl[nf][0] = *(const uint32_t*)&sBl[r * LDK + kk];
                bl[nf][1] = *(const uint32_t*)&sBl[r * LDK + kk + 8];
            }
            #pragma unroll
            for (int mf = 0; mf < 4; mf++)
                #pragma unroll
                for (int nf = 0; nf < 4; nf++) {
                    mma16816(acc[mf][nf], ah[mf][0], ah[mf][1], ah[mf][2], ah[mf][3],
                             bh[nf][0], bh[nf][1]);
                    mma16816(acc[mf][nf], ah[mf][0], ah[mf][1], ah[mf][2], ah[mf][3],
                             bl[nf][0], bl[nf][1]);
                    mma16816(acc[mf][nf], al[mf][0], al[mf][1], al[mf][2], al[mf][3],
                             bh[nf][0], bh[nf][1]);
                }
        }
        __syncthreads();
    }
    #undef PREFETCH

    // ---- epilogue ----
    #pragma unroll
    for (int mf = 0; mf < 4; mf++) {
        const int ra = m0 + wm * 64 + mf * 16 + g;
        #pragma unroll
        for (int nf = 0; nf < 4; nf++) {
            const int col = n0 + wn * 32 + nf * 8 + tg * 2;
            const float b0 = bias[col], b1 = bias[col + 1];
            #pragma unroll
            for (int half = 0; half < 2; half++) {
                const int r = ra + half * 8;
                const float v0 = acc[mf][nf][half * 2 + 0] + b0;
                const float v1 = acc[mf][nf][half * 2 + 1] + b1;
                if (GELU) {
                    const float g0 = 0.5f * v0 * (1.0f + erff(v0 * 0.70710678118654752f));
                    const float g1 = 0.5f * v1 * (1.0f + erff(v1 * 0.70710678118654752f));
                    __nv_bfloat16 h0 = __float2bfloat16(g0);
                    __nv_bfloat16 h1 = __float2bfloat16(g1);
                    __nv_bfloat162 hp; hp.x = h0; hp.y = h1;
                    __nv_bfloat162 lp;
                    lp.x = __float2bfloat16(g0 - __bfloat162float(h0));
                    lp.y = __float2bfloat16(g1 - __bfloat162float(h1));
                    *(__nv_bfloat162*)&Ohi[(size_t)r * N + col] = hp;
                    *(__nv_bfloat162*)&Olo[(size_t)r * N + col] = lp;
                } else {
                    const float2 rr = *(const float2*)&res[(size_t)r * N + col];
                    float2 o = make_float2(v0 + rr.x, v1 + rr.y);
                    *(float2*)&Of[(size_t)r * N + col] = o;
                }
            }
        }
    }
}

// ---------------- launch ----------------------------------------------------
extern "C" void kernel_launch(void* const* d_in, const int* in_sizes, int n_in,
                              void* d_out, int out_size) {
    const float* x   = (const float*)d_in[0];
    const float* w1  = (const float*)d_in[1];
    const float* b1  = (const float*)d_in[2];
    const float* w2  = (const float*)d_in[3];
    const float* b2  = (const float*)d_in[4];
    const float* g1  = (const float*)d_in[5];
    const float* be1 = (const float*)d_in[6];
    const float* g2  = (const float*)d_in[7];
    const float* be2 = (const float*)d_in[8];
    float* out = (float*)d_out;

    float *fr, *fi, *h;
    __nv_bfloat16 *acth, *actl, *w1h, *w1l, *w2h, *w2l;
    cudaGetSymbolAddress((void**)&fr,   g_fr);
    cudaGetSymbolAddress((void**)&fi,   g_fi);
    cudaGetSymbolAddress((void**)&h,    g_h);
    cudaGetSymbolAddress((void**)&acth, g_act_hi);
    cudaGetSymbolAddress((void**)&actl, g_act_lo);
    cudaGetSymbolAddress((void**)&w1h,  g_w1t_hi);
    cudaGetSymbolAddress((void**)&w1l,  g_w1t_lo);
    cudaGetSymbolAddress((void**)&w2h,  g_w2t_hi);
    cudaGetSymbolAddress((void**)&w2l,  g_w2t_lo);

    // reuse g_fr (free after add_ln) as bf16 hi/lo storage for h
    __nv_bfloat16* hh = (__nv_bfloat16*)fr;
    __nv_bfloat16* hl = hh + (size_t)TOT;

    cudaFuncSetAttribute(mma_gemm_kernel<0>,
                         cudaFuncAttributeMaxDynamicSharedMemorySize, GEMM_SMEM);
    cudaFuncSetAttribute(mma_gemm_kernel<1>,
                         cudaFuncAttributeMaxDynamicSharedMemorySize, GEMM_SMEM);
    cudaFuncSetAttribute(fft_seq_kernel,
                         cudaFuncAttributeMaxDynamicSharedMemorySize, SEQ_SMEM);

    // 1. twiddles + weight prep
    twiddle_init_kernel<<<8, 256>>>();
    transpose_split_kernel<<<dim3(FF / 32, HID / 32), dim3(32, 8)>>>(w1, w1h, w1l, HID, FF);
    transpose_split_kernel<<<dim3(HID / 32, FF / 32), dim3(32, 8)>>>(w2, w2h, w2l, FF, HID);
    // 2. FFT over hidden dim -> (g_fr, g_fi)
    fft_hidden_kernel<<<NROWS, 256>>>(x);
    // 3. FFT over seq dim (4 columns/block), real part -> g_fr (= x_ft)
    fft_seq_kernel<<<BATCH * HID / 4, 512, SEQ_SMEM>>>();
    // 4. h = LN1(x + x_ft)
    add_ln_kernel<<<NROWS, 256>>>(x, fr, g1, be1, h);
    // 5. split h -> bf16 hi/lo (g_fr reused)
    split_kernel<<<TOT / 1024, 256>>>(h, hh, hl);
    // 6. act(hi/lo bf16) = gelu(h @ w1 + b1)
    mma_gemm_kernel<1><<<dim3(FF / 128, NROWS / 128), 256, GEMM_SMEM>>>(
        hh, hl, w1h, w1l, b1, nullptr, acth, actl, nullptr, NROWS, FF, HID);
    // 7. y = act @ w2 + b2 + h -> g_fi
    mma_gemm_kernel<0><<<dim3(HID / 128, NROWS / 128), 256, GEMM_SMEM>>>(
        acth, actl, w2h, w2l, b2, h, nullptr, nullptr, fi, NROWS, HID, FF);
    // 8. out = LN2(y)
    add_ln_kernel<<<NROWS, 256>>>(fi, nullptr, g2, be2, out);
}

// round 10
// speedup vs baseline: 2.4360x; 1.0423x over previous
#include <cuda_runtime.h>
#include <cuda_bf16.h>
#include <math.h>
#include <stdint.h>

#define BATCH 4
#define SEQ   4096
#define HID   1024
#define FF    4096
#define NROWS (BATCH*SEQ)          // 16384
#define TOT   (NROWS*HID)          // 16777216

// ---------------- scratch (static device arrays; no allocation allowed) ----
__device__ float  g_fr[TOT];                 // x_ft
__device__ float  g_fi[TOT];                 // fft imag; then h hi/lo; then y
__device__ float  g_h [TOT];                 // h = LN1(x + x_ft)
__device__ __nv_bfloat16 g_act_hi[(size_t)NROWS*FF];
__device__ __nv_bfloat16 g_act_lo[(size_t)NROWS*FF];
__device__ __nv_bfloat16 g_w1t_hi[(size_t)HID*FF];  // [FF][HID] K-major
__device__ __nv_bfloat16 g_w1t_lo[(size_t)HID*FF];
__device__ __nv_bfloat16 g_w2t_hi[(size_t)HID*FF];  // [HID][FF] K-major
__device__ __nv_bfloat16 g_w2t_lo[(size_t)HID*FF];
__device__ float2 g_tw[2048];                // e^{-2*pi*i*j/4096}

// ============================================================================
// PTX helpers (arch-generic: mma.sync + cp.async + ldmatrix)
// ============================================================================
__device__ __forceinline__ uint32_t smem_u32(const void* p) {
    uint32_t a;
    asm("{ .reg .u64 t; cvta.to.shared.u64 t, %1; cvt.u32.u64 %0, t; }"
        : "=r"(a) : "l"(p));
    return a;
}
__device__ __forceinline__ void mma16816(float* d,
                                         uint32_t a0, uint32_t a1, uint32_t a2, uint32_t a3,
                                         uint32_t b0, uint32_t b1) {
    asm volatile(
        "mma.sync.aligned.m16n8k16.row.col.f32.bf16.bf16.f32 "
        "{%0,%1,%2,%3}, {%4,%5,%6,%7}, {%8,%9}, {%0,%1,%2,%3};"
        : "+f"(d[0]), "+f"(d[1]), "+f"(d[2]), "+f"(d[3])
        : "r"(a0), "r"(a1), "r"(a2), "r"(a3), "r"(b0), "r"(b1));
}
#define LDM_X4(r0, r1, r2, r3, addr) \
    asm volatile("ldmatrix.sync.aligned.m8n8.x4.shared.b16 {%0,%1,%2,%3}, [%4];" \
        : "=r"(r0), "=r"(r1), "=r"(r2), "=r"(r3) : "r"(addr))
#define LDM_X2(r0, r1, addr) \
    asm volatile("ldmatrix.sync.aligned.m8n8.x2.shared.b16 {%0,%1}, [%2];" \
        : "=r"(r0), "=r"(r1) : "r"(addr))
#define CP_ASYNC16(dst_u32, src_ptr) \
    asm volatile("cp.async.cg.shared.global [%0], [%1], 16;" \
        :: "r"(dst_u32), "l"(src_ptr))
#define CP_COMMIT() asm volatile("cp.async.commit_group;" ::: "memory")
#define CP_WAIT(n)  asm volatile("cp.async.wait_group %0;" :: "n"(n) : "memory")

__device__ __forceinline__ float2 cmul(float2 a, float2 b) {
    return make_float2(a.x * b.x - a.y * b.y, a.y * b.x + a.x * b.y);
}

// ---------------- twiddle init ---------------------------------------------
__global__ void twiddle_init_kernel() {
    int j = blockIdx.x * blockDim.x + threadIdx.x;
    if (j < 2048) {
        float ang = -6.283185307179586f * (float)j / 4096.0f;
        float s, c;
        sincosf(ang, &s, &c);
        g_tw[j] = make_float2(c, s);
    }
}

// ---------------- weight transpose + hi/lo split ----------------------------
__global__ void transpose_split_kernel(const float* __restrict__ W,
                                       __nv_bfloat16* __restrict__ Thi,
                                       __nv_bfloat16* __restrict__ Tlo,
                                       int K, int N) {
    __shared__ float t[32][33];
    const int n = blockIdx.x * 32 + threadIdx.x;
    const int k0 = blockIdx.y * 32;
    #pragma unroll
    for (int j = 0; j < 32; j += 8)
        t[threadIdx.y + j][threadIdx.x] = W[(size_t)(k0 + threadIdx.y + j) * N + n];
    __syncthreads();
    const int k = k0 + threadIdx.x;
    #pragma unroll
    for (int j = 0; j < 32; j += 8) {
        float v = t[threadIdx.x][threadIdx.y + j];
        __nv_bfloat16 hi = __float2bfloat16(v);
        float lo = v - __bfloat162float(hi);
        size_t o = (size_t)(blockIdx.x * 32 + threadIdx.y + j) * K + k;
        Thi[o] = hi;
        Tlo[o] = __float2bfloat16(lo);
    }
}

// ---------------- FFT over hidden dim (N=1024), radix-4, one row/block -----
#define SWB10(i) ((i) ^ (((i) >> 5) & 31))
__global__ void fft_hidden_kernel(const float* __restrict__ x) {
    __shared__ float2 sc[1024];
    const int row = blockIdx.x;
    const float* xp = x + (size_t)row * HID;
    for (int i = threadIdx.x; i < 1024; i += 256) {
        int r = __brev((unsigned)i) >> 22;
        sc[SWB10(r)] = make_float2(xp[i], 0.f);
    }
    __syncthreads();
    // 5 radix-4 passes merging stage pairs (s, s+1), s = 1,3,5,7,9
    #pragma unroll
    for (int p = 0; p < 5; p++) {
        const int s = 2 * p + 1;
        const int q = 1 << (s - 1);
        const int j = threadIdx.x;                 // 256 butterflies
        const int k  = j & (q - 1);
        const int i0 = ((j >> (s - 1)) << (s + 1)) + k;
        const float2 w1 = g_tw[k << (12 - s)];
        const float2 w2 = g_tw[k << (11 - s)];
        float2 a = sc[SWB10(i0)];
        float2 b = sc[SWB10(i0 + q)];
        float2 c = sc[SWB10(i0 + 2 * q)];
        float2 d = sc[SWB10(i0 + 3 * q)];
        float2 wb = cmul(w1, b), wd = cmul(w1, d);
        float2 A = make_float2(a.x + wb.x, a.y + wb.y);
        float2 B = make_float2(a.x - wb.x, a.y - wb.y);
        float2 C = make_float2(c.x + wd.x, c.y + wd.y);
        float2 D = make_float2(c.x - wd.x, c.y - wd.y);
        float2 wC = cmul(w2, C), wD = cmul(w2, D);
        __syncthreads();                           // reads done before writes
        sc[SWB10(i0)]         = make_float2(A.x + wC.x, A.y + wC.y);
        sc[SWB10(i0 + 2 * q)] = make_float2(A.x - wC.x, A.y - wC.y);
        sc[SWB10(i0 + q)]     = make_float2(B.x + wD.y, B.y - wD.x);  // -i*wD
        sc[SWB10(i0 + 3 * q)] = make_float2(B.x - wD.y, B.y + wD.x);
        __syncthreads();
    }
    float* fr = g_fr + (size_t)row * HID;
    float* fi = g_fi + (size_t)row * HID;
    for (int i = threadIdx.x; i < 1024; i += 256) {
        float2 v = sc[SWB10(i)];
        fr[i] = v.x;
        fi[i] = v.y;
    }
}

// ---------------- FFT over seq dim (N=4096), radix-4, 4 columns/block ------
#define SWB12(i) ((i) ^ (((i) >> 7) & 31))
#define SEQ_SMEM (4 * 4096 * (int)sizeof(float2))   // 128 KB
__global__ void fft_seq_kernel() {
    extern __shared__ float2 sc4[];                 // [4][4096]
    const int col0 = blockIdx.x * 4;
    const int b    = col0 >> 10;
    const int h0   = col0 & 1023;
    const size_t base = (size_t)b * SEQ * HID + h0;

    for (int i = threadIdx.x; i < 4096; i += 512) {
        int r = SWB12(__brev((unsigned)i) >> 20);
        float4 vr = *(const float4*)(g_fr + base + (size_t)i * HID);
        float4 vi = *(const float4*)(g_fi + base + (size_t)i * HID);
        sc4[0 * 4096 + r] = make_float2(vr.x, vi.x);
        sc4[1 * 4096 + r] = make_float2(vr.y, vi.y);
        sc4[2 * 4096 + r] = make_float2(vr.z, vi.z);
        sc4[3 * 4096 + r] = make_float2(vr.w, vi.w);
    }
    __syncthreads();

    {
        const int c  = threadIdx.x >> 7;            // 0..3, warp-uniform
        const int jb = threadIdx.x & 127;
        float2* cs = sc4 + c * 4096;
        // 6 radix-4 passes, s = 1,3,5,7,9,11
        #pragma unroll
        for (int p = 0; p < 6; p++) {
            const int s = 2 * p + 1;
            const int q = 1 << (s - 1);
            #pragma unroll
            for (int j = jb; j < 1024; j += 128) {  // 1024 butterflies/column
                const int k  = j & (q - 1);
                const int i0 = ((j >> (s - 1)) << (s + 1)) + k;
                const float2 w1 = g_tw[k << (12 - s)];
                const float2 w2 = g_tw[k << (11 - s)];
                float2 a = cs[SWB12(i0)];
                float2 bb = cs[SWB12(i0 + q)];
                float2 cc = cs[SWB12(i0 + 2 * q)];
                float2 d = cs[SWB12(i0 + 3 * q)];
                float2 wb = cmul(w1, bb), wd = cmul(w1, d);
                float2 A = make_float2(a.x + wb.x, a.y + wb.y);
                float2 B = make_float2(a.x - wb.x, a.y - wb.y);
                float2 C = make_float2(cc.x + wd.x, cc.y + wd.y);
                float2 D = make_float2(cc.x - wd.x, cc.y - wd.y);
                float2 wC = cmul(w2, C), wD = cmul(w2, D);
                cs[SWB12(i0)]         = make_float2(A.x + wC.x, A.y + wC.y);
                cs[SWB12(i0 + 2 * q)] = make_float2(A.x - wC.x, A.y - wC.y);
                cs[SWB12(i0 + q)]     = make_float2(B.x + wD.y, B.y - wD.x);
                cs[SWB12(i0 + 3 * q)] = make_float2(B.x - wD.y, B.y + wD.x);
            }
            __syncthreads();
        }
    }

    for (int i = threadIdx.x; i < 4096; i += 512) {
        int si = SWB12(i);
        float4 o = make_float4(sc4[0 * 4096 + si].x, sc4[1 * 4096 + si].x,
                               sc4[2 * 4096 + si].x, sc4[3 * 4096 + si].x);
        *(float4*)(g_fr + base + (size_t)i * HID) = o;   // real part only
    }
}

// ---------------- out = LayerNorm(a [+ b]); optional bf16 hi/lo split ------
__global__ void add_ln_kernel(const float* __restrict__ a,
                              const float* __restrict__ badd,
                              const float* __restrict__ gamma,
                              const float* __restrict__ beta,
                              float* __restrict__ out,
                              __nv_bfloat16* __restrict__ ohi,
                              __nv_bfloat16* __restrict__ olo) {
    const int row = blockIdx.x;
    const int tid = threadIdx.x;
    const float4* a4 = (const float4*)(a + (size_t)row * HID);
    float4 v = a4[tid];
    if (badd) {
        const float4* b4 = (const float4*)(badd + (size_t)row * HID);
        float4 w = b4[tid];
        v.x += w.x; v.y += w.y; v.z += w.z; v.w += w.w;
    }
    float sum = v.x + v.y + v.z + v.w;
    float sq  = v.x*v.x + v.y*v.y + v.z*v.z + v.w*v.w;
    __shared__ float s1[8], s2[8];
    #pragma unroll
    for (int o = 16; o > 0; o >>= 1) {
        sum += __shfl_xor_sync(0xffffffffu, sum, o);
        sq  += __shfl_xor_sync(0xffffffffu, sq,  o);
    }
    const int warp = tid >> 5, lane = tid & 31;
    if (lane == 0) { s1[warp] = sum; s2[warp] = sq; }
    __syncthreads();
    if (warp == 0) {
        float a1 = (lane < 8) ? s1[lane] : 0.f;
        float a2 = (lane < 8) ? s2[lane] : 0.f;
        #pragma unroll
        for (int o = 4; o > 0; o >>= 1) {
            a1 += __shfl_xor_sync(0xffffffffu, a1, o);
            a2 += __shfl_xor_sync(0xffffffffu, a2, o);
        }
        if (lane == 0) { s1[0] = a1; s2[0] = a2; }
    }
    __syncthreads();
    const float mu  = s1[0] * (1.0f / 1024.0f);
    const float var = s2[0] * (1.0f / 1024.0f) - mu * mu;
    const float inv = rsqrtf(var + 1e-5f);
    const float4 g  = ((const float4*)gamma)[tid];
    const float4 bt = ((const float4*)beta)[tid];
    float o[4];
    o[0] = (v.x - mu) * inv * g.x + bt.x;
    o[1] = (v.y - mu) * inv * g.y + bt.y;
    o[2] = (v.z - mu) * inv * g.z + bt.z;
    o[3] = (v.w - mu) * inv * g.w + bt.w;
    ((float4*)(out + (size_t)row * HID))[tid] = *(float4*)o;
    if (ohi) {
        __nv_bfloat16 h[4], l[4];
        #pragma unroll
        for (int e = 0; e < 4; e++) {
            h[e] = __float2bfloat16(o[e]);
            l[e] = __float2bfloat16(o[e] - __bfloat162float(h[e]));
        }
        const size_t off = (size_t)row * HID + tid * 4;
        *(uint2*)(ohi + off) = *(uint2*)h;
        *(uint2*)(olo + off) = *(uint2*)l;
    }
}

// ============================================================================
// bf16 split GEMM on mma.sync.m16n8k16.  CTA tile 128x128, BK=32, 8 warps,
// warp tile 64x32.  3-stage cp.async pipeline + ldmatrix fragment loads.
// 3 split terms: Ahi*Bhi + Ahi*Blo + Alo*Bhi into fp32 accumulators.
// GELU=1: C = gelu(A@B + bias) -> bf16 hi/lo.   GELU=0: C = A@B+bias+res (f32)
// ============================================================================
#define LDK 40                      // padded row stride (bf16 elems), 80 bytes
#define BUF_BYTES (128 * LDK * 2)   // 10240 B
#define STAGES 3
#define GEMM_SMEM (STAGES * 4 * BUF_BYTES)   // 122880 B

template<int GELU>
__global__ void __launch_bounds__(256)
mma_gemm_kernel(const __nv_bfloat16* __restrict__ Ahi,
                const __nv_bfloat16* __restrict__ Alo,
                const __nv_bfloat16* __restrict__ Bhi,
                const __nv_bfloat16* __restrict__ Blo,
                const float* __restrict__ bias,
                const float* __restrict__ res,
                __nv_bfloat16* __restrict__ Ohi,
                __nv_bfloat16* __restrict__ Olo,
                float* __restrict__ Of,
                int M, int N, int K)
{
    extern __shared__ __nv_bfloat16 smem[];   // [STAGES][4 bufs][128][LDK]
    const int tid  = threadIdx.x;
    const int wid  = tid >> 5;
    const int lane = tid & 31;
    const int wm = wid >> 2;        // 0..1
    const int wn = wid & 3;         // 0..3
    const int g  = lane >> 2;       // 0..7
    const int tg = lane & 3;        // 0..3
    const int m0 = blockIdx.y * 128;
    const int n0 = blockIdx.x * 128;

    // cp.async mapping: 16B per thread per 64-row half per buffer
    const int r0c = tid >> 2;              // rows 0..63
    const int kc0 = (tid & 3) * 8;         // bf16 elem offset within BK=32
    const uint32_t sbase = smem_u32(smem);

    // ldmatrix per-thread addresses
    const int arow = wm * 64 + (lane & 7) + ((lane >> 3) & 1) * 8;  // +mf*16
    const int acol = (lane >> 4) * 8;                               // +ks*16
    const uint32_t aoff = (uint32_t)(arow * LDK + acol) * 2;
    const int brow = wn * 32 + (lane & 7);                          // +nf*8
    const int bcol = ((lane >> 3) & 1) * 8;                         // +ks*16
    const uint32_t boff = (uint32_t)(brow * LDK + bcol) * 2;

    const __nv_bfloat16* srcA[2] = {Ahi, Alo};
    const __nv_bfloat16* srcB[2] = {Bhi, Blo};

    float acc[4][4][4];
    #pragma unroll
    for (int i = 0; i < 4; i++)
        #pragma unroll
        for (int j = 0; j < 4; j++)
            #pragma unroll
            for (int e = 0; e < 4; e++) acc[i][j][e] = 0.f;

    const int NC = K >> 5;          // K / 32

    #define PREFETCH(cidx, stage) do {                                         \
        const int _k0 = (cidx) << 5;                                           \
        uint32_t _sb = sbase + (stage) * 4 * BUF_BYTES;                        \
        _Pragma("unroll")                                                      \
        for (int _h = 0; _h < 2; _h++) {                                       \
            _Pragma("unroll")                                                  \
            for (int _half = 0; _half < 2; _half++) {                          \
                int _row = r0c + _half * 64;                                   \
                uint32_t _d = _sb + (_h) * BUF_BYTES +                         \
                              (_row * LDK + kc0) * 2;                          \
                CP_ASYNC16(_d, srcA[_h] + (size_t)(m0 + _row) * K + _k0 + kc0);\
                uint32_t _d2 = _sb + (2 + _h) * BUF_BYTES +                    \
                               (_row * LDK + kc0) * 2;                         \
                CP_ASYNC16(_d2, srcB[_h] + (size_t)(n0 + _row) * K + _k0 + kc0);\
            }                                                                  \
        }                                                                      \
        CP_COMMIT();                                                           \
    } while (0)

    PREFETCH(0, 0);
    PREFETCH(1, 1);

    int st = 0;
    for (int c = 0; c < NC; c++) {
        if (c + 2 < NC) {
            int ps = (st + 2 >= STAGES) ? st + 2 - STAGES : st + 2;
            PREFETCH(c + 2, ps);
            CP_WAIT(2);
        } else if (c + 1 < NC) {
            CP_WAIT(1);
        } else {
            CP_WAIT(0);
        }
        __syncthreads();

        const uint32_t sAh = sbase + (st * 4 + 0) * BUF_BYTES;
        const uint32_t sAl = sbase + (st * 4 + 1) * BUF_BYTES;
        const uint32_t sBh = sbase + (st * 4 + 2) * BUF_BYTES;
        const uint32_t sBl = sbase + (st * 4 + 3) * BUF_BYTES;

        #pragma unroll
        for (int ks = 0; ks < 2; ks++) {
            uint32_t ah[4][4], al[4][4], bh[4][2], bl[4][2];
            #pragma unroll
            for (int mf = 0; mf < 4; mf++) {
                const uint32_t ao = aoff + mf * (16 * LDK * 2) + ks * 32;
                LDM_X4(ah[mf][0], ah[mf][1], ah[mf][2], ah[mf][3], sAh + ao);
                LDM_X4(al[mf][0], al[mf][1], al[mf][2], al[mf][3], sAl + ao);
            }
            #pragma unroll
            for (int nf = 0; nf < 4; nf++) {
                const uint32_t bo = boff + nf * (8 * LDK * 2) + ks * 32;
                LDM_X2(bh[nf][0], bh[nf][1], sBh + bo);
                LDM_X2(bl[nf][0], bl[nf][1], sBl + bo);
            }
            #pragma unroll
            for (int mf = 0; mf < 4; mf++)
                #pragma unroll
                for (int nf = 0; nf < 4; nf++) {
                    mma16816(acc[mf][nf], ah[mf][0], ah[mf][1], ah[mf][2], ah[mf][3],
                             bh[nf][0], bh[nf][1]);
                    mma16816(acc[mf][nf], ah[mf][0], ah[mf][1], ah[mf][2], ah[mf][3],
                             bl[nf][0], bl[nf][1]);
                    mma16816(acc[mf][nf], al[mf][0], al[mf][1], al[mf][2], al[mf][3],
                             bh[nf][0], bh[nf][1]);
                }
        }
        __syncthreads();
        st = (st + 1 >= STAGES) ? 0 : st + 1;
    }
    #undef PREFETCH

    // ---- epilogue ----
    #pragma unroll
    for (int mf = 0; mf < 4; mf++) {
        const int ra = m0 + wm * 64 + mf * 16 + g;
        #pragma unroll
        for (int nf = 0; nf < 4; nf++) {
            const int col = n0 + wn * 32 + nf * 8 + tg * 2;
            const float b0 = bias[col], b1 = bias[col + 1];
            #pragma unroll
            for (int half = 0; half < 2; half++) {
                const int r = ra + half * 8;
                const float v0 = acc[mf][nf][half * 2 + 0] + b0;
                const float v1 = acc[mf][nf][half * 2 + 1] + b1;
                if (GELU) {
                    const float g0 = 0.5f * v0 * (1.0f + erff(v0 * 0.70710678118654752f));
                    const float g1 = 0.5f * v1 * (1.0f + erff(v1 * 0.70710678118654752f));
                    __nv_bfloat16 h0 = __float2bfloat16(g0);
                    __nv_bfloat16 h1 = __float2bfloat16(g1);
                    __nv_bfloat162 hp; hp.x = h0; hp.y = h1;
                    __nv_bfloat162 lp;
                    lp.x = __float2bfloat16(g0 - __bfloat162float(h0));
                    lp.y = __float2bfloat16(g1 - __bfloat162float(h1));
                    *(__nv_bfloat162*)&Ohi[(size_t)r * N + col] = hp;
                    *(__nv_bfloat162*)&Olo[(size_t)r * N + col] = lp;
                } else {
                    const float2 rr = *(const float2*)&res[(size_t)r * N + col];
                    float2 o = make_float2(v0 + rr.x, v1 + rr.y);
                    *(float2*)&Of[(size_t)r * N + col] = o;
                }
            }
        }
    }
}

// ---------------- launch ----------------------------------------------------
extern "C" void kernel_launch(void* const* d_in, const int* in_sizes, int n_in,
                              void* d_out, int out_size) {
    const float* x   = (const float*)d_in[0];
    const float* w1  = (const float*)d_in[1];
    const float* b1  = (const float*)d_in[2];
    const float* w2  = (const float*)d_in[3];
    const float* b2  = (const float*)d_in[4];
    const float* g1  = (const float*)d_in[5];
    const float* be1 = (const float*)d_in[6];
    const float* g2  = (const float*)d_in[7];
    const float* be2 = (const float*)d_in[8];
    float* out = (float*)d_out;

    float *fr, *fi, *h;
    __nv_bfloat16 *acth, *actl, *w1h, *w1l, *w2h, *w2l;
    cudaGetSymbolAddress((void**)&fr,   g_fr);
    cudaGetSymbolAddress((void**)&fi,   g_fi);
    cudaGetSymbolAddress((void**)&h,    g_h);
    cudaGetSymbolAddress((void**)&acth, g_act_hi);
    cudaGetSymbolAddress((void**)&actl, g_act_lo);
    cudaGetSymbolAddress((void**)&w1h,  g_w1t_hi);
    cudaGetSymbolAddress((void**)&w1l,  g_w1t_lo);
    cudaGetSymbolAddress((void**)&w2h,  g_w2t_hi);
    cudaGetSymbolAddress((void**)&w2l,  g_w2t_lo);

    // h hi/lo split lives in g_fi (dead between fft_seq output consumption
    // and GEMM2's y output; GEMM2 overwrites it only after acth/actl are read)
    __nv_bfloat16* hh = (__nv_bfloat16*)fi;
    __nv_bfloat16* hl = hh + (size_t)TOT;

    cudaFuncSetAttribute(mma_gemm_kernel<0>,
                         cudaFuncAttributeMaxDynamicSharedMemorySize, GEMM_SMEM);
    cudaFuncSetAttribute(mma_gemm_kernel<1>,
                         cudaFuncAttributeMaxDynamicSharedMemorySize, GEMM_SMEM);
    cudaFuncSetAttribute(fft_seq_kernel,
                         cudaFuncAttributeMaxDynamicSharedMemorySize, SEQ_SMEM);

    // 1. twiddles + weight prep
    twiddle_init_kernel<<<8, 256>>>();
    transpose_split_kernel<<<dim3(FF / 32, HID / 32), dim3(32, 8)>>>(w1, w1h, w1l, HID, FF);
    transpose_split_kernel<<<dim3(HID / 32, FF / 32), dim3(32, 8)>>>(w2, w2h, w2l, FF, HID);
    // 2. FFT over hidden dim -> (g_fr, g_fi)
    fft_hidden_kernel<<<NROWS, 256>>>(x);
    // 3. FFT over seq dim (4 columns/block), real part -> g_fr (= x_ft)
    fft_seq_kernel<<<BATCH * HID / 4, 512, SEQ_SMEM>>>();
    // 4. h = LN1(x + x_ft), fused bf16 hi/lo split into g_fi
    add_ln_kernel<<<NROWS, 256>>>(x, fr, g1, be1, h, hh, hl);
    // 5. act(hi/lo bf16) = gelu(h @ w1 + b1)
    mma_gemm_kernel<1><<<dim3(FF / 128, NROWS / 128), 256, GEMM_SMEM>>>(
        hh, hl, w1h, w1l, b1, nullptr, acth, actl, nullptr, NROWS, FF, HID);
    // 6. y = act @ w2 + b2 + h -> g_fi (overwrites dead hh/hl)
    mma_gemm_kernel<0><<<dim3(HID / 128, NROWS / 128), 256, GEMM_SMEM>>>(
        acth, actl, w2h, w2l, b2, h, nullptr, nullptr, fi, NROWS, HID, FF);
    // 7. out = LN2(y)
    add_ln_kernel<<<NROWS, 256>>>(fi, nullptr, g2, be2, out, nullptr, nullptr);
}

// round 12
// speedup vs baseline: 2.5642x; 1.0526x over previous
#include <cuda_runtime.h>
#include <cuda_bf16.h>
#include <math.h>
#include <stdint.h>

#define BATCH 4
#define SEQ   4096
#define HID   1024
#define FF    4096
#define NROWS (BATCH*SEQ)          // 16384
#define TOT   (NROWS*HID)          // 16777216

// ---------------- scratch (static device arrays; no allocation allowed) ----
__device__ float  g_fr[TOT];                 // x_ft
__device__ float  g_fi[TOT];                 // fft imag; then h hi/lo; then y
__device__ float  g_h [TOT];                 // h = LN1(x + x_ft)
__device__ __nv_bfloat16 g_act_hi[(size_t)NROWS*FF];
__device__ __nv_bfloat16 g_act_lo[(size_t)NROWS*FF];
__device__ __nv_bfloat16 g_w1t_hi[(size_t)HID*FF];  // [FF][HID] K-major
__device__ __nv_bfloat16 g_w1t_lo[(size_t)HID*FF];
__device__ __nv_bfloat16 g_w2t_hi[(size_t)HID*FF];  // [HID][FF] K-major
__device__ __nv_bfloat16 g_w2t_lo[(size_t)HID*FF];
__device__ float2 g_tw[2048];                // e^{-2*pi*i*j/4096}

// ============================================================================
// PTX helpers (arch-generic: mma.sync + cp.async + ldmatrix)
// ============================================================================
__device__ __forceinline__ uint32_t smem_u32(const void* p) {
    uint32_t a;
    asm("{ .reg .u64 t; cvta.to.shared.u64 t, %1; cvt.u32.u64 %0, t; }"
        : "=r"(a) : "l"(p));
    return a;
}
__device__ __forceinline__ void mma16816(float* d,
                                         uint32_t a0, uint32_t a1, uint32_t a2, uint32_t a3,
                                         uint32_t b0, uint32_t b1) {
    asm volatile(
        "mma.sync.aligned.m16n8k16.row.col.f32.bf16.bf16.f32 "
        "{%0,%1,%2,%3}, {%4,%5,%6,%7}, {%8,%9}, {%0,%1,%2,%3};"
        : "+f"(d[0]), "+f"(d[1]), "+f"(d[2]), "+f"(d[3])
        : "r"(a0), "r"(a1), "r"(a2), "r"(a3), "r"(b0), "r"(b1));
}
#define LDM_X4(r0, r1, r2, r3, addr) \
    asm volatile("ldmatrix.sync.aligned.m8n8.x4.shared.b16 {%0,%1,%2,%3}, [%4];" \
        : "=r"(r0), "=r"(r1), "=r"(r2), "=r"(r3) : "r"(addr))
#define CP_ASYNC16(dst_u32, src_ptr) \
    asm volatile("cp.async.cg.shared.global [%0], [%1], 16;" \
        :: "r"(dst_u32), "l"(src_ptr))
#define CP_COMMIT() asm volatile("cp.async.commit_group;" ::: "memory")
#define CP_WAIT(n)  asm volatile("cp.async.wait_group %0;" :: "n"(n) : "memory")

__device__ __forceinline__ float2 cmul(float2 a, float2 b) {
    return make_float2(a.x * b.x - a.y * b.y, a.y * b.x + a.x * b.y);
}

// ---------------- twiddle init ---------------------------------------------
__global__ void twiddle_init_kernel() {
    int j = blockIdx.x * blockDim.x + threadIdx.x;
    if (j < 2048) {
        float ang = -6.283185307179586f * (float)j / 4096.0f;
        float s, c;
        sincosf(ang, &s, &c);
        g_tw[j] = make_float2(c, s);
    }
}

// ---------------- weight transpose + hi/lo split ----------------------------
__global__ void transpose_split_kernel(const float* __restrict__ W,
                                       __nv_bfloat16* __restrict__ Thi,
                                       __nv_bfloat16* __restrict__ Tlo,
                                       int K, int N) {
    __shared__ float t[32][33];
    const int n = blockIdx.x * 32 + threadIdx.x;
    const int k0 = blockIdx.y * 32;
    #pragma unroll
    for (int j = 0; j < 32; j += 8)
        t[threadIdx.y + j][threadIdx.x] = W[(size_t)(k0 + threadIdx.y + j) * N + n];
    __syncthreads();
    const int k = k0 + threadIdx.x;
    #pragma unroll
    for (int j = 0; j < 32; j += 8) {
        float v = t[threadIdx.x][threadIdx.y + j];
        __nv_bfloat16 hi = __float2bfloat16(v);
        float lo = v - __bfloat162float(hi);
        size_t o = (size_t)(blockIdx.x * 32 + threadIdx.y + j) * K + k;
        Thi[o] = hi;
        Tlo[o] = __float2bfloat16(lo);
    }
}

// ---------------- FFT over hidden dim (N=1024), radix-4, one row/block -----
// One butterfly per thread per pass; per-pass index sets are disjoint across
// threads, so only ONE barrier per pass is needed.
#define SWB10(i) ((i) ^ (((i) >> 5) & 31))
__global__ void fft_hidden_kernel(const float* __restrict__ x) {
    __shared__ float2 sc[1024];
    const int row = blockIdx.x;
    const float* xp = x + (size_t)row * HID;
    for (int i = threadIdx.x; i < 1024; i += 256) {
        int r = __brev((unsigned)i) >> 22;
        sc[SWB10(r)] = make_float2(xp[i], 0.f);
    }
    __syncthreads();
    #pragma unroll
    for (int p = 0; p < 5; p++) {
        const int s = 2 * p + 1;
        const int q = 1 << (s - 1);
        const int j = threadIdx.x;                 // 256 butterflies
        const int k  = j & (q - 1);
        const int i0 = ((j >> (s - 1)) << (s + 1)) + k;
        const float2 w1 = g_tw[k << (12 - s)];
        const float2 w2 = g_tw[k << (11 - s)];
        float2 a = sc[SWB10(i0)];
        float2 b = sc[SWB10(i0 + q)];
        float2 c = sc[SWB10(i0 + 2 * q)];
        float2 d = sc[SWB10(i0 + 3 * q)];
        float2 wb = cmul(w1, b), wd = cmul(w1, d);
        float2 A = make_float2(a.x + wb.x, a.y + wb.y);
        float2 B = make_float2(a.x - wb.x, a.y - wb.y);
        float2 C = make_float2(c.x + wd.x, c.y + wd.y);
        float2 D = make_float2(c.x - wd.x, c.y - wd.y);
        float2 wC = cmul(w2, C), wD = cmul(w2, D);
        sc[SWB10(i0)]         = make_float2(A.x + wC.x, A.y + wC.y);
        sc[SWB10(i0 + 2 * q)] = make_float2(A.x - wC.x, A.y - wC.y);
        sc[SWB10(i0 + q)]     = make_float2(B.x + wD.y, B.y - wD.x);  // -i*wD
        sc[SWB10(i0 + 3 * q)] = make_float2(B.x - wD.y, B.y + wD.x);
        __syncthreads();
    }
    float* fr = g_fr + (size_t)row * HID;
    float* fi = g_fi + (size_t)row * HID;
    for (int i = threadIdx.x; i < 1024; i += 256) {
        float2 v = sc[SWB10(i)];
        fr[i] = v.x;
        fi[i] = v.y;
    }
}

// ---------------- FFT over seq dim (N=4096), radix-4, 4 columns/block ------
#define SWB12(i) ((i) ^ (((i) >> 7) & 31))
#define SEQ_SMEM (4 * 4096 * (int)sizeof(float2))   // 128 KB
__global__ void fft_seq_kernel() {
    extern __shared__ float2 sc4[];                 // [4][4096]
    const int col0 = blockIdx.x * 4;
    const int b    = col0 >> 10;
    const int h0   = col0 & 1023;
    const size_t base = (size_t)b * SEQ * HID + h0;

    for (int i = threadIdx.x; i < 4096; i += 512) {
        int r = SWB12(__brev((unsigned)i) >> 20);
        float4 vr = *(const float4*)(g_fr + base + (size_t)i * HID);
        float4 vi = *(const float4*)(g_fi + base + (size_t)i * HID);
        sc4[0 * 4096 + r] = make_float2(vr.x, vi.x);
        sc4[1 * 4096 + r] = make_float2(vr.y, vi.y);
        sc4[2 * 4096 + r] = make_float2(vr.z, vi.z);
        sc4[3 * 4096 + r] = make_float2(vr.w, vi.w);
    }
    __syncthreads();

    {
        const int c  = threadIdx.x >> 7;            // 0..3, warp-uniform
        const int jb = threadIdx.x & 127;
        float2* cs = sc4 + c * 4096;
        #pragma unroll
        for (int p = 0; p < 6; p++) {
            const int s = 2 * p + 1;
            const int q = 1 << (s - 1);
            #pragma unroll
            for (int j = jb; j < 1024; j += 128) {  // 1024 butterflies/column
                const int k  = j & (q - 1);
                const int i0 = ((j >> (s - 1)) << (s + 1)) + k;
                const float2 w1 = g_tw[k << (12 - s)];
                const float2 w2 = g_tw[k << (11 - s)];
                float2 a = cs[SWB12(i0)];
                float2 bb = cs[SWB12(i0 + q)];
                float2 cc = cs[SWB12(i0 + 2 * q)];
                float2 d = cs[SWB12(i0 + 3 * q)];
                float2 wb = cmul(w1, bb), wd = cmul(w1, d);
                float2 A = make_float2(a.x + wb.x, a.y + wb.y);
                float2 B = make_float2(a.x - wb.x, a.y - wb.y);
                float2 C = make_float2(cc.x + wd.x, cc.y + wd.y);
                float2 D = make_float2(cc.x - wd.x, cc.y - wd.y);
                float2 wC = cmul(w2, C), wD = cmul(w2, D);
                cs[SWB12(i0)]         = make_float2(A.x + wC.x, A.y + wC.y);
                cs[SWB12(i0 + 2 * q)] = make_float2(A.x - wC.x, A.y - wC.y);
                cs[SWB12(i0 + q)]     = make_float2(B.x + wD.y, B.y - wD.x);
                cs[SWB12(i0 + 3 * q)] = make_float2(B.x - wD.y, B.y + wD.x);
            }
            __syncthreads();
        }
    }

    for (int i = threadIdx.x; i < 4096; i += 512) {
        int si = SWB12(i);
        float4 o = make_float4(sc4[0 * 4096 + si].x, sc4[1 * 4096 + si].x,
                               sc4[2 * 4096 + si].x, sc4[3 * 4096 + si].x);
        *(float4*)(g_fr + base + (size_t)i * HID) = o;   // real part only
    }
}

// ---------------- out = LayerNorm(a [+ b]); optional bf16 hi/lo split ------
__global__ void add_ln_kernel(const float* __restrict__ a,
                              const float* __restrict__ badd,
                              const float* __restrict__ gamma,
                              const float* __restrict__ beta,
                              float* __restrict__ out,
                              __nv_bfloat16* __restrict__ ohi,
                              __nv_bfloat16* __restrict__ olo) {
    const int row = blockIdx.x;
    const int tid = threadIdx.x;
    const float4* a4 = (const float4*)(a + (size_t)row * HID);
    float4 v = a4[tid];
    if (badd) {
        const float4* b4 = (const float4*)(badd + (size_t)row * HID);
        float4 w = b4[tid];
        v.x += w.x; v.y += w.y; v.z += w.z; v.w += w.w;
    }
    float sum = v.x + v.y + v.z + v.w;
    float sq  = v.x*v.x + v.y*v.y + v.z*v.z + v.w*v.w;
    __shared__ float s1[8], s2[8];
    #pragma unroll
    for (int o = 16; o > 0; o >>= 1) {
        sum += __shfl_xor_sync(0xffffffffu, sum, o);
        sq  += __shfl_xor_sync(0xffffffffu, sq,  o);
    }
    const int warp = tid >> 5, lane = tid & 31;
    if (lane == 0) { s1[warp] = sum; s2[warp] = sq; }
    __syncthreads();
    if (warp == 0) {
        float a1 = (lane < 8) ? s1[lane] : 0.f;
        float a2 = (lane < 8) ? s2[lane] : 0.f;
        #pragma unroll
        for (int o = 4; o > 0; o >>= 1) {
            a1 += __shfl_xor_sync(0xffffffffu, a1, o);
            a2 += __shfl_xor_sync(0xffffffffu, a2, o);
        }
        if (lane == 0) { s1[0] = a1; s2[0] = a2; }
    }
    __syncthreads();
    const float mu  = s1[0] * (1.0f / 1024.0f);
    const float var = s2[0] * (1.0f / 1024.0f) - mu * mu;
    const float inv = rsqrtf(var + 1e-5f);
    const float4 g  = ((const float4*)gamma)[tid];
    const float4 bt = ((const float4*)beta)[tid];
    float o[4];
    o[0] = (v.x - mu) * inv * g.x + bt.x;
    o[1] = (v.y - mu) * inv * g.y + bt.y;
    o[2] = (v.z - mu) * inv * g.z + bt.z;
    o[3] = (v.w - mu) * inv * g.w + bt.w;
    ((float4*)(out + (size_t)row * HID))[tid] = *(float4*)o;
    if (ohi) {
        __nv_bfloat16 h[4], l[4];
        #pragma unroll
        for (int e = 0; e < 4; e++) {
            h[e] = __float2bfloat16(o[e]);
            l[e] = __float2bfloat16(o[e] - __bfloat162float(h[e]));
        }
        const size_t off = (size_t)row * HID + tid * 4;
        *(uint2*)(ohi + off) = *(uint2*)h;
        *(uint2*)(olo + off) = *(uint2*)l;
    }
}

// ============================================================================
// bf16 split GEMM on mma.sync.m16n8k16.  CTA tile 128x128, BK=32, 8 warps,
// warp tile 64x32.  4-stage cp.async pipeline, ONE barrier per chunk,
// ldmatrix.x4 fragment loads (A: 4 per term, B: 2 per term per ks).
// 3 split terms: Ahi*Bhi + Ahi*Blo + Alo*Bhi into fp32 accumulators.
// GELU=1: C = gelu(A@B + bias) -> bf16 hi/lo.   GELU=0: C = A@B+bias+res (f32)
// ============================================================================
#define LDK 40                      // padded row stride (bf16 elems), 80 bytes
#define BUF_BYTES (128 * LDK * 2)   // 10240 B
#define STAGES 4
#define GEMM_SMEM (STAGES * 4 * BUF_BYTES)   // 163840 B

template<int GELU>
__global__ void __launch_bounds__(256)
mma_gemm_kernel(const __nv_bfloat16* __restrict__ Ahi,
                const __nv_bfloat16* __restrict__ Alo,
                const __nv_bfloat16* __restrict__ Bhi,
                const __nv_bfloat16* __restrict__ Blo,
                const float* __restrict__ bias,
                const float* __restrict__ res,
                __nv_bfloat16* __restrict__ Ohi,
                __nv_bfloat16* __restrict__ Olo,
                float* __restrict__ Of,
                int M, int N, int K)
{
    extern __shared__ __nv_bfloat16 smem[];   // [STAGES][4 bufs][128][LDK]
    const int tid  = threadIdx.x;
    const int wid  = tid >> 5;
    const int lane = tid & 31;
    const int wm = wid >> 2;        // 0..1
    const int wn = wid & 3;         // 0..3
    const int g  = lane >> 2;       // 0..7
    const int tg = lane & 3;        // 0..3
    const int m0 = blockIdx.y * 128;
    const int n0 = blockIdx.x * 128;

    // cp.async mapping: 16B per thread per 64-row half per buffer
    const int r0c = tid >> 2;              // rows 0..63
    const int kc0 = (tid & 3) * 8;         // bf16 elem offset within BK=32
    const uint32_t sbase = smem_u32(smem);

    // ldmatrix A addresses: x4 -> (row g, col0/col8) x (row g / row g+8)
    const int arow = wm * 64 + (lane & 7) + ((lane >> 3) & 1) * 8;  // +mf*16
    const int acol = (lane >> 4) * 8;                               // +ks*16
    const uint32_t aoff = (uint32_t)(arow * LDK + acol) * 2;
    // ldmatrix B addresses: x4 covering nf-pair:
    //   m0,m1 = (nf, col0/col8); m2,m3 = (nf+1, col0/col8)
    const int brow = wn * 32 + (lane & 7) + ((lane >> 4) & 1) * 8;  // +pair*16
    const int bcol = ((lane >> 3) & 1) * 8;                         // +ks*16
    const uint32_t boff = (uint32_t)(brow * LDK + bcol) * 2;

    const __nv_bfloat16* srcA[2] = {Ahi, Alo};
    const __nv_bfloat16* srcB[2] = {Bhi, Blo};

    float acc[4][4][4];
    #pragma unroll
    for (int i = 0; i < 4; i++)
        #pragma unroll
        for (int j = 0; j < 4; j++)
            #pragma unroll
            for (int e = 0; e < 4; e++) acc[i][j][e] = 0.f;

    const int NC = K >> 5;          // K / 32

    // Always commits exactly one group (empty if cidx >= NC).
    #define PREFETCH(cidx, stage) do {                                         \
        if ((cidx) < NC) {                                                     \
            const int _k0 = (cidx) << 5;                                       \
            uint32_t _sb = sbase + (stage) * 4 * BUF_BYTES;                    \
            _Pragma("unroll")                                                  \
            for (int _h = 0; _h < 2; _h++) {                                   \
                _Pragma("unroll")                                              \
                for (int _half = 0; _half < 2; _half++) {                      \
                    int _row = r0c + _half * 64;                               \
                    uint32_t _d = _sb + (_h) * BUF_BYTES +                     \
                                  (_row * LDK + kc0) * 2;                      \
                    CP_ASYNC16(_d, srcA[_h] + (size_t)(m0 + _row) * K + _k0 + kc0);  \
                    uint32_t _d2 = _sb + (2 + _h) * BUF_BYTES +                \
                                   (_row * LDK + kc0) * 2;                     \
                    CP_ASYNC16(_d2, srcB[_h] + (size_t)(n0 + _row) * K + _k0 + kc0); \
                }                                                              \
            }                                                                  \
        }                                                                      \
        CP_COMMIT();                                                           \
    } while (0)

    PREFETCH(0, 0);
    PREFETCH(1, 1);
    PREFETCH(2, 2);

    int st = 0;
    for (int c = 0; c < NC; c++) {
        // pending groups after the 3-deep prologue + 1 commit/iter is always
        // (3 + c) - (c + 1) = 2 once chunk c completes
        CP_WAIT(2);
        __syncthreads();
        // prefetch into stage (st+3)%4: every warp finished computing it
        // (it was chunk c-1's read stage ... no: it is the stage 3 ahead,
        //  last read at chunk c-4, and all warps passed barrier of chunk c-3+)
        PREFETCH(c + 3, (st + 3) & (STAGES - 1));

        const uint32_t sAh = sbase + (st * 4 + 0) * BUF_BYTES;
        const uint32_t sAl = sbase + (st * 4 + 1) * BUF_BYTES;
        const uint32_t sBh = sbase + (st * 4 + 2) * BUF_BYTES;
        const uint32_t sBl = sbase + (st * 4 + 3) * BUF_BYTES;

        #pragma unroll
        for (int ks = 0; ks < 2; ks++) {
            uint32_t ah[4][4], al[4][4], bh[4][2], bl[4][2];
            #pragma unroll
            for (int mf = 0; mf < 4; mf++) {
                const uint32_t ao = aoff + mf * (16 * LDK * 2) + ks * 32;
                LDM_X4(ah[mf][0], ah[mf][1], ah[mf][2], ah[mf][3], sAh + ao);
                LDM_X4(al[mf][0], al[mf][1], al[mf][2], al[mf][3], sAl + ao);
            }
            #pragma unroll
            for (int pr = 0; pr < 2; pr++) {       // nf pairs {0,1}, {2,3}
                const uint32_t bo = boff + pr * (16 * LDK * 2) + ks * 32;
                LDM_X4(bh[pr*2][0], bh[pr*2][1], bh[pr*2+1][0], bh[pr*2+1][1], sBh + bo);
                LDM_X4(bl[pr*2][0], bl[pr*2][1], bl[pr*2+1][0], bl[pr*2+1][1], sBl + bo);
            }
            #pragma unroll
            for (int mf = 0; mf < 4; mf++)
                #pragma unroll
                for (int nf = 0; nf < 4; nf++) {
                    mma16816(acc[mf][nf], ah[mf][0], ah[mf][1], ah[mf][2], ah[mf][3],
                             bh[nf][0], bh[nf][1]);
                    mma16816(acc[mf][nf], ah[mf][0], ah[mf][1], ah[mf][2], ah[mf][3],
                             bl[nf][0], bl[nf][1]);
                    mma16816(acc[mf][nf], al[mf][0], al[mf][1], al[mf][2], al[mf][3],
                             bh[nf][0], bh[nf][1]);
                }
        }
        st = (st + 1) & (STAGES - 1);
    }
    #undef PREFETCH

    // ---- epilogue ----
    #pragma unroll
    for (int mf = 0; mf < 4; mf++) {
        const int ra = m0 + wm * 64 + mf * 16 + g;
        #pragma unroll
        for (int nf = 0; nf < 4; nf++) {
            const int col = n0 + wn * 32 + nf * 8 + tg * 2;
            const float b0 = bias[col], b1 = bias[col + 1];
            #pragma unroll
            for (int half = 0; half < 2; half++) {
                const int r = ra + half * 8;
                const float v0 = acc[mf][nf][half * 2 + 0] + b0;
                const float v1 = acc[mf][nf][half * 2 + 1] + b1;
                if (GELU) {
                    const float g0 = 0.5f * v0 * (1.0f + erff(v0 * 0.70710678118654752f));
                    const float g1 = 0.5f * v1 * (1.0f + erff(v1 * 0.70710678118654752f));
                    __nv_bfloat16 h0 = __float2bfloat16(g0);
                    __nv_bfloat16 h1 = __float2bfloat16(g1);
                    __nv_bfloat162 hp; hp.x = h0; hp.y = h1;
                    __nv_bfloat162 lp;
                    lp.x = __float2bfloat16(g0 - __bfloat162float(h0));
                    lp.y = __float2bfloat16(g1 - __bfloat162float(h1));
                    *(__nv_bfloat162*)&Ohi[(size_t)r * N + col] = hp;
                    *(__nv_bfloat162*)&Olo[(size_t)r * N + col] = lp;
                } else {
                    const float2 rr = *(const float2*)&res[(size_t)r * N + col];
                    float2 o = make_float2(v0 + rr.x, v1 + rr.y);
                    *(float2*)&Of[(size_t)r * N + col] = o;
                }
            }
        }
    }
}

// ---------------- launch ----------------------------------------------------
extern "C" void kernel_launch(void* const* d_in, const int* in_sizes, int n_in,
                              void* d_out, int out_size) {
    const float* x   = (const float*)d_in[0];
    const float* w1  = (const float*)d_in[1];
    const float* b1  = (const float*)d_in[2];
    const float* w2  = (const float*)d_in[3];
    const float* b2  = (const float*)d_in[4];
    const float* g1  = (const float*)d_in[5];
    const float* be1 = (const float*)d_in[6];
    const float* g2  = (const float*)d_in[7];
    const float* be2 = (const float*)d_in[8];
    float* out = (float*)d_out;

    float *fr, *fi, *h;
    __nv_bfloat16 *acth, *actl, *w1h, *w1l, *w2h, *w2l;
    cudaGetSymbolAddress((void**)&fr,   g_fr);
    cudaGetSymbolAddress((void**)&fi,   g_fi);
    cudaGetSymbolAddress((void**)&h,    g_h);
    cudaGetSymbolAddress((void**)&acth, g_act_hi);
    cudaGetSymbolAddress((void**)&actl, g_act_lo);
    cudaGetSymbolAddress((void**)&w1h,  g_w1t_hi);
    cudaGetSymbolAddress((void**)&w1l,  g_w1t_lo);
    cudaGetSymbolAddress((void**)&w2h,  g_w2t_hi);
    cudaGetSymbolAddress((void**)&w2l,  g_w2t_lo);

    // h hi/lo split lives in g_fi (dead after LN1 consumes fft imag part;
    // GEMM2 overwrites it only after acth/actl were produced from it)
    __nv_bfloat16* hh = (__nv_bfloat16*)fi;
    __nv_bfloat16* hl = hh + (size_t)TOT;

    cudaFuncSetAttribute(mma_gemm_kernel<0>,
                         cudaFuncAttributeMaxDynamicSharedMemorySize, GEMM_SMEM);
    cudaFuncSetAttribute(mma_gemm_kernel<1>,
                         cudaFuncAttributeMaxDynamicSharedMemorySize, GEMM_SMEM);
    cudaFuncSetAttribute(fft_seq_kernel,
                         cudaFuncAttributeMaxDynamicSharedMemorySize, SEQ_SMEM);

    // 1. twiddles + weight prep
    twiddle_init_kernel<<<8, 256>>>();
    transpose_split_kernel<<<dim3(FF / 32, HID / 32), dim3(32, 8)>>>(w1, w1h, w1l, HID, FF);
    transpose_split_kernel<<<dim3(HID / 32, FF / 32), dim3(32, 8)>>>(w2, w2h, w2l, FF, HID);
    // 2. FFT over hidden dim -> (g_fr, g_fi)
    fft_hidden_kernel<<<NROWS, 256>>>(x);
    // 3. FFT over seq dim (4 columns/block), real part -> g_fr (= x_ft)
    fft_seq_kernel<<<BATCH * HID / 4, 512, SEQ_SMEM>>>();
    // 4. h = LN1(x + x_ft), fused bf16 hi/lo split into g_fi
    add_ln_kernel<<<NROWS, 256>>>(x, fr, g1, be1, h, hh, hl);
    // 5. act(hi/lo bf16) = gelu(h @ w1 + b1)
    mma_gemm_kernel<1><<<dim3(FF / 128, NROWS / 128), 256, GEMM_SMEM>>>(
        hh, hl, w1h, w1l, b1, nullptr, acth, actl, nullptr, NROWS, FF, HID);
    // 6. y = act @ w2 + b2 + h -> g_fi (overwrites dead hh/hl)
    mma_gemm_kernel<0><<<dim3(HID / 128, NROWS / 128), 256, GEMM_SMEM>>>(
        acth, actl, w2h, w2l, b2, h, nullptr, nullptr, fi, NROWS, HID, FF);
    // 7. out = LN2(y)
    add_ln_kernel<<<NROWS, 256>>>(fi, nullptr, g2, be2, out, nullptr, nullptr);
}

// round 14
// speedup vs baseline: 2.9073x; 1.1338x over previous
#include <cuda_runtime.h>
#include <cuda_bf16.h>
#include <math.h>
#include <stdint.h>

#define BATCH 4
#define SEQ   4096
#define HID   1024
#define FF    4096
#define NROWS (BATCH*SEQ)          // 16384
#define TOT   (NROWS*HID)          // 16777216

// ---------------- scratch (static device arrays; no allocation allowed) ----
__device__ float  g_fr[TOT];                 // x_ft
__device__ float  g_fi[TOT];                 // fft imag; then h hi/lo; then y
__device__ float  g_h [TOT];                 // h = LN1(x + x_ft)
__device__ __nv_bfloat16 g_act_hi[(size_t)NROWS*FF];
__device__ __nv_bfloat16 g_act_lo[(size_t)NROWS*FF];
__device__ __nv_bfloat16 g_w1t_hi[(size_t)HID*FF];  // [FF][HID] K-major
__device__ __nv_bfloat16 g_w1t_lo[(size_t)HID*FF];
__device__ __nv_bfloat16 g_w2t_hi[(size_t)HID*FF];  // [HID][FF] K-major
__device__ __nv_bfloat16 g_w2t_lo[(size_t)HID*FF];
__device__ float2 g_tw[2048];                // e^{-2*pi*i*j/4096}

// ============================================================================
// PTX helpers (arch-generic: mma.sync + cp.async + ldmatrix)
// ============================================================================
__device__ __forceinline__ uint32_t smem_u32(const void* p) {
    uint32_t a;
    asm("{ .reg .u64 t; cvta.to.shared.u64 t, %1; cvt.u32.u64 %0, t; }"
        : "=r"(a) : "l"(p));
    return a;
}
__device__ __forceinline__ void mma16816(float* d,
                                         uint32_t a0, uint32_t a1, uint32_t a2, uint32_t a3,
                                         uint32_t b0, uint32_t b1) {
    asm volatile(
        "mma.sync.aligned.m16n8k16.row.col.f32.bf16.bf16.f32 "
        "{%0,%1,%2,%3}, {%4,%5,%6,%7}, {%8,%9}, {%0,%1,%2,%3};"
        : "+f"(d[0]), "+f"(d[1]), "+f"(d[2]), "+f"(d[3])
        : "r"(a0), "r"(a1), "r"(a2), "r"(a3), "r"(b0), "r"(b1));
}
#define LDM_X4(r0, r1, r2, r3, addr) \
    asm volatile("ldmatrix.sync.aligned.m8n8.x4.shared.b16 {%0,%1,%2,%3}, [%4];" \
        : "=r"(r0), "=r"(r1), "=r"(r2), "=r"(r3) : "r"(addr))
#define CP_ASYNC16(dst_u32, src_ptr) \
    asm volatile("cp.async.cg.shared.global [%0], [%1], 16;" \
        :: "r"(dst_u32), "l"(src_ptr))
#define CP_COMMIT() asm volatile("cp.async.commit_group;" ::: "memory")
#define CP_WAIT(n)  asm volatile("cp.async.wait_group %0;" :: "n"(n) : "memory")

__device__ __forceinline__ float2 cmul(float2 a, float2 b) {
    return make_float2(a.x * b.x - a.y * b.y, a.y * b.x + a.x * b.y);
}

// ---------------- twiddle init ---------------------------------------------
__global__ void twiddle_init_kernel() {
    int j = blockIdx.x * blockDim.x + threadIdx.x;
    if (j < 2048) {
        float ang = -6.283185307179586f * (float)j / 4096.0f;
        float s, c;
        sincosf(ang, &s, &c);
        g_tw[j] = make_float2(c, s);
    }
}

// ---------------- weight transpose + hi/lo split ----------------------------
__global__ void transpose_split_kernel(const float* __restrict__ W,
                                       __nv_bfloat16* __restrict__ Thi,
                                       __nv_bfloat16* __restrict__ Tlo,
                                       int K, int N) {
    __shared__ float t[32][33];
    const int n = blockIdx.x * 32 + threadIdx.x;
    const int k0 = blockIdx.y * 32;
    #pragma unroll
    for (int j = 0; j < 32; j += 8)
        t[threadIdx.y + j][threadIdx.x] = W[(size_t)(k0 + threadIdx.y + j) * N + n];
    __syncthreads();
    const int k = k0 + threadIdx.x;
    #pragma unroll
    for (int j = 0; j < 32; j += 8) {
        float v = t[threadIdx.x][threadIdx.y + j];
        __nv_bfloat16 hi = __float2bfloat16(v);
        float lo = v - __bfloat162float(hi);
        size_t o = (size_t)(blockIdx.x * 32 + threadIdx.y + j) * K + k;
        Thi[o] = hi;
        Tlo[o] = __float2bfloat16(lo);
    }
}

// ---------------- FFT over hidden dim (N=1024), radix-4, one row/block -----
#define SWB10(i) ((i) ^ (((i) >> 5) & 31))
__global__ void fft_hidden_kernel(const float* __restrict__ x) {
    __shared__ float2 sc[1024];
    const int row = blockIdx.x;
    const float* xp = x + (size_t)row * HID;
    for (int i = threadIdx.x; i < 1024; i += 256) {
        int r = __brev((unsigned)i) >> 22;
        sc[SWB10(r)] = make_float2(xp[i], 0.f);
    }
    __syncthreads();
    #pragma unroll
    for (int p = 0; p < 5; p++) {
        const int s = 2 * p + 1;
        const int q = 1 << (s - 1);
        const int j = threadIdx.x;                 // 256 butterflies
        const int k  = j & (q - 1);
        const int i0 = ((j >> (s - 1)) << (s + 1)) + k;
        const float2 w1 = g_tw[k << (12 - s)];
        const float2 w2 = g_tw[k << (11 - s)];
        float2 a = sc[SWB10(i0)];
        float2 b = sc[SWB10(i0 + q)];
        float2 c = sc[SWB10(i0 + 2 * q)];
        float2 d = sc[SWB10(i0 + 3 * q)];
        float2 wb = cmul(w1, b), wd = cmul(w1, d);
        float2 A = make_float2(a.x + wb.x, a.y + wb.y);
        float2 B = make_float2(a.x - wb.x, a.y - wb.y);
        float2 C = make_float2(c.x + wd.x, c.y + wd.y);
        float2 D = make_float2(c.x - wd.x, c.y - wd.y);
        float2 wC = cmul(w2, C), wD = cmul(w2, D);
        sc[SWB10(i0)]         = make_float2(A.x + wC.x, A.y + wC.y);
        sc[SWB10(i0 + 2 * q)] = make_float2(A.x - wC.x, A.y - wC.y);
        sc[SWB10(i0 + q)]     = make_float2(B.x + wD.y, B.y - wD.x);  // -i*wD
        sc[SWB10(i0 + 3 * q)] = make_float2(B.x - wD.y, B.y + wD.x);
        __syncthreads();
    }
    float* fr = g_fr + (size_t)row * HID;
    float* fi = g_fi + (size_t)row * HID;
    for (int i = threadIdx.x; i < 1024; i += 256) {
        float2 v = sc[SWB10(i)];
        fr[i] = v.x;
        fi[i] = v.y;
    }
}

// ---------------- FFT over seq dim (N=4096), radix-4, 4 columns/block ------
#define SWB12(i) ((i) ^ (((i) >> 7) & 31))
#define SEQ_SMEM (4 * 4096 * (int)sizeof(float2))   // 128 KB
__global__ void fft_seq_kernel() {
    extern __shared__ float2 sc4[];                 // [4][4096]
    const int col0 = blockIdx.x * 4;
    const int b    = col0 >> 10;
    const int h0   = col0 & 1023;
    const size_t base = (size_t)b * SEQ * HID + h0;

    for (int i = threadIdx.x; i < 4096; i += 512) {
        int r = SWB12(__brev((unsigned)i) >> 20);
        float4 vr = *(const float4*)(g_fr + base + (size_t)i * HID);
        float4 vi = *(const float4*)(g_fi + base + (size_t)i * HID);
        sc4[0 * 4096 + r] = make_float2(vr.x, vi.x);
        sc4[1 * 4096 + r] = make_float2(vr.y, vi.y);
        sc4[2 * 4096 + r] = make_float2(vr.z, vi.z);
        sc4[3 * 4096 + r] = make_float2(vr.w, vi.w);
    }
    __syncthreads();

    {
        const int c  = threadIdx.x >> 7;            // 0..3, warp-uniform
        const int jb = threadIdx.x & 127;
        float2* cs = sc4 + c * 4096;
        #pragma unroll
        for (int p = 0; p < 6; p++) {
            const int s = 2 * p + 1;
            const int q = 1 << (s - 1);
            #pragma unroll
            for (int j = jb; j < 1024; j += 128) {  // 1024 butterflies/column
                const int k  = j & (q - 1);
                const int i0 = ((j >> (s - 1)) << (s + 1)) + k;
                const float2 w1 = g_tw[k << (12 - s)];
                const float2 w2 = g_tw[k << (11 - s)];
                float2 a = cs[SWB12(i0)];
                float2 bb = cs[SWB12(i0 + q)];
                float2 cc = cs[SWB12(i0 + 2 * q)];
                float2 d = cs[SWB12(i0 + 3 * q)];
                float2 wb = cmul(w1, bb), wd = cmul(w1, d);
                float2 A = make_float2(a.x + wb.x, a.y + wb.y);
                float2 B = make_float2(a.x - wb.x, a.y - wb.y);
                float2 C = make_float2(cc.x + wd.x, cc.y + wd.y);
                float2 D = make_float2(cc.x - wd.x, cc.y - wd.y);
                float2 wC = cmul(w2, C), wD = cmul(w2, D);
                cs[SWB12(i0)]         = make_float2(A.x + wC.x, A.y + wC.y);
                cs[SWB12(i0 + 2 * q)] = make_float2(A.x - wC.x, A.y - wC.y);
                cs[SWB12(i0 + q)]     = make_float2(B.x + wD.y, B.y - wD.x);
                cs[SWB12(i0 + 3 * q)] = make_float2(B.x - wD.y, B.y + wD.x);
            }
            __syncthreads();
        }
    }

    for (int i = threadIdx.x; i < 4096; i += 512) {
        int si = SWB12(i);
        float4 o = make_float4(sc4[0 * 4096 + si].x, sc4[1 * 4096 + si].x,
                               sc4[2 * 4096 + si].x, sc4[3 * 4096 + si].x);
        *(float4*)(g_fr + base + (size_t)i * HID) = o;   // real part only
    }
}

// ---------------- out = LayerNorm(a [+ b]); optional bf16 hi/lo split ------
__global__ void add_ln_kernel(const float* __restrict__ a,
                              const float* __restrict__ badd,
                              const float* __restrict__ gamma,
                              const float* __restrict__ beta,
                              float* __restrict__ out,
                              __nv_bfloat16* __restrict__ ohi,
                              __nv_bfloat16* __restrict__ olo) {
    const int row = blockIdx.x;
    const int tid = threadIdx.x;
    const float4* a4 = (const float4*)(a + (size_t)row * HID);
    float4 v = a4[tid];
    if (badd) {
        const float4* b4 = (const float4*)(badd + (size_t)row * HID);
        float4 w = b4[tid];
        v.x += w.x; v.y += w.y; v.z += w.z; v.w += w.w;
    }
    float sum = v.x + v.y + v.z + v.w;
    float sq  = v.x*v.x + v.y*v.y + v.z*v.z + v.w*v.w;
    __shared__ float s1[8], s2[8];
    #pragma unroll
    for (int o = 16; o > 0; o >>= 1) {
        sum += __shfl_xor_sync(0xffffffffu, sum, o);
        sq  += __shfl_xor_sync(0xffffffffu, sq,  o);
    }
    const int warp = tid >> 5, lane = tid & 31;
    if (lane == 0) { s1[warp] = sum; s2[warp] = sq; }
    __syncthreads();
    if (warp == 0) {
        float a1 = (lane < 8) ? s1[lane] : 0.f;
        float a2 = (lane < 8) ? s2[lane] : 0.f;
        #pragma unroll
        for (int o = 4; o > 0; o >>= 1) {
            a1 += __shfl_xor_sync(0xffffffffu, a1, o);
            a2 += __shfl_xor_sync(0xffffffffu, a2, o);
        }
        if (lane == 0) { s1[0] = a1; s2[0] = a2; }
    }
    __syncthreads();
    const float mu  = s1[0] * (1.0f / 1024.0f);
    const float var = s2[0] * (1.0f / 1024.0f) - mu * mu;
    const float inv = rsqrtf(var + 1e-5f);
    const float4 g  = ((const float4*)gamma)[tid];
    const float4 bt = ((const float4*)beta)[tid];
    float o[4];
    o[0] = (v.x - mu) * inv * g.x + bt.x;
    o[1] = (v.y - mu) * inv * g.y + bt.y;
    o[2] = (v.z - mu) * inv * g.z + bt.z;
    o[3] = (v.w - mu) * inv * g.w + bt.w;
    ((float4*)(out + (size_t)row * HID))[tid] = *(float4*)o;
    if (ohi) {
        __nv_bfloat16 h[4], l[4];
        #pragma unroll
        for (int e = 0; e < 4; e++) {
            h[e] = __float2bfloat16(o[e]);
            l[e] = __float2bfloat16(o[e] - __bfloat162float(h[e]));
        }
        const size_t off = (size_t)row * HID + tid * 4;
        *(uint2*)(ohi + off) = *(uint2*)h;
        *(uint2*)(olo + off) = *(uint2*)l;
    }
}

// ============================================================================
// bf16 split GEMM on mma.sync.m16n8k16.  CTA tile 128x128, BK=32, 8 warps,
// warp tile 64x32.  2-stage cp.async pipeline, ONE barrier per chunk,
// 2 CTAs/SM (80KB smem each) for cross-CTA latency hiding.
// 3 split terms: Ahi*Bhi + Ahi*Blo + Alo*Bhi into fp32 accumulators.
// GELU=1: C = gelu(A@B + bias) -> bf16 hi/lo.   GELU=0: C = A@B+bias+res (f32)
// ============================================================================
#define LDK 40                      // padded row stride (bf16 elems), 80 bytes
#define BUF_BYTES (128 * LDK * 2)   // 10240 B
#define STAGES 2
#define GEMM_SMEM (STAGES * 4 * BUF_BYTES)   // 81920 B

template<int GELU>
__global__ void __launch_bounds__(256, 2)
mma_gemm_kernel(const __nv_bfloat16* __restrict__ Ahi,
                const __nv_bfloat16* __restrict__ Alo,
                const __nv_bfloat16* __restrict__ Bhi,
                const __nv_bfloat16* __restrict__ Blo,
                const float* __restrict__ bias,
                const float* __restrict__ res,
                __nv_bfloat16* __restrict__ Ohi,
                __nv_bfloat16* __restrict__ Olo,
                float* __restrict__ Of,
                int M, int N, int K)
{
    extern __shared__ __nv_bfloat16 smem[];   // [STAGES][4 bufs][128][LDK]
    const int tid  = threadIdx.x;
    const int wid  = tid >> 5;
    const int lane = tid & 31;
    const int wm = wid >> 2;        // 0..1
    const int wn = wid & 3;         // 0..3
    const int g  = lane >> 2;       // 0..7
    const int tg = lane & 3;        // 0..3
    const int m0 = blockIdx.y * 128;
    const int n0 = blockIdx.x * 128;

    // cp.async mapping: 16B per thread per 64-row half per buffer
    const int r0c = tid >> 2;              // rows 0..63
    const int kc0 = (tid & 3) * 8;         // bf16 elem offset within BK=32
    const uint32_t sbase = smem_u32(smem);

    // ldmatrix A addresses: x4 -> rows g/g+8 x cols 0/8
    const int arow = wm * 64 + (lane & 7) + ((lane >> 3) & 1) * 8;  // +mf*16
    const int acol = (lane >> 4) * 8;                               // +ks*16
    const uint32_t aoff = (uint32_t)(arow * LDK + acol) * 2;
    // ldmatrix B addresses: x4 covering nf-pair
    const int brow = wn * 32 + (lane & 7) + ((lane >> 4) & 1) * 8;  // +pair*16
    const int bcol = ((lane >> 3) & 1) * 8;                         // +ks*16
    const uint32_t boff = (uint32_t)(brow * LDK + bcol) * 2;

    const __nv_bfloat16* srcA[2] = {Ahi, Alo};
    const __nv_bfloat16* srcB[2] = {Bhi, Blo};

    float acc[4][4][4];
    #pragma unroll
    for (int i = 0; i < 4; i++)
        #pragma unroll
        for (int j = 0; j < 4; j++)
            #pragma unroll
            for (int e = 0; e < 4; e++) acc[i][j][e] = 0.f;

    const int NC = K >> 5;          // K / 32

    // Always commits exactly one group (empty if cidx >= NC).
    #define PREFETCH(cidx, stage) do {                                         \
        if ((cidx) < NC) {                                                     \
            const int _k0 = (cidx) << 5;                                       \
            uint32_t _sb = sbase + (stage) * 4 * BUF_BYTES;                    \
            _Pragma("unroll")                                                  \
            for (int _h = 0; _h < 2; _h++) {                                   \
                _Pragma("unroll")                                              \
                for (int _half = 0; _half < 2; _half++) {                      \
                    int _row = r0c + _half * 64;                               \
                    uint32_t _d = _sb + (_h) * BUF_BYTES +                     \
                                  (_row * LDK + kc0) * 2;                      \
                    CP_ASYNC16(_d, srcA[_h] + (size_t)(m0 + _row) * K + _k0 + kc0);  \
                    uint32_t _d2 = _sb + (2 + _h) * BUF_BYTES +                \
                                   (_row * LDK + kc0) * 2;                     \
                    CP_ASYNC16(_d2, srcB[_h] + (size_t)(n0 + _row) * K + _k0 + kc0); \
                }                                                              \
            }                                                                  \
        }                                                                      \
        CP_COMMIT();                                                           \
    } while (0)

    PREFETCH(0, 0);

    for (int c = 0; c < NC; c++) {
        const int st = c & 1;
        CP_WAIT(0);
        __syncthreads();
        // stage st^1's last readers finished chunk c-1 before this barrier
        PREFETCH(c + 1, st ^ 1);

        const uint32_t sAh = sbase + (st * 4 + 0) * BUF_BYTES;
        const uint32_t sAl = sbase + (st * 4 + 1) * BUF_BYTES;
        const uint32_t sBh = sbase + (st * 4 + 2) * BUF_BYTES;
        const uint32_t sBl = sbase + (st * 4 + 3) * BUF_BYTES;

        #pragma unroll
        for (int ks = 0; ks < 2; ks++) {
            uint32_t bh[4][2], bl[4][2];
            #pragma unroll
            for (int pr = 0; pr < 2; pr++) {       // nf pairs {0,1}, {2,3}
                const uint32_t bo = boff + pr * (16 * LDK * 2) + ks * 32;
                LDM_X4(bh[pr*2][0], bh[pr*2][1], bh[pr*2+1][0], bh[pr*2+1][1], sBh + bo);
                LDM_X4(bl[pr*2][0], bl[pr*2][1], bl[pr*2+1][0], bl[pr*2+1][1], sBl + bo);
            }
            #pragma unroll
            for (int mf = 0; mf < 4; mf++) {
                uint32_t ah[4], al[4];
                const uint32_t ao = aoff + mf * (16 * LDK * 2) + ks * 32;
                LDM_X4(ah[0], ah[1], ah[2], ah[3], sAh + ao);
                LDM_X4(al[0], al[1], al[2], al[3], sAl + ao);
                #pragma unroll
                for (int nf = 0; nf < 4; nf++) {
                    mma16816(acc[mf][nf], ah[0], ah[1], ah[2], ah[3],
                             bh[nf][0], bh[nf][1]);
                    mma16816(acc[mf][nf], ah[0], ah[1], ah[2], ah[3],
                             bl[nf][0], bl[nf][1]);
                    mma16816(acc[mf][nf], al[0], al[1], al[2], al[3],
                             bh[nf][0], bh[nf][1]);
                }
            }
        }
    }
    #undef PREFETCH

    // ---- epilogue ----
    #pragma unroll
    for (int mf = 0; mf < 4; mf++) {
        const int ra = m0 + wm * 64 + mf * 16 + g;
        #pragma unroll
        for (int nf = 0; nf < 4; nf++) {
            const int col = n0 + wn * 32 + nf * 8 + tg * 2;
            const float b0 = bias[col], b1 = bias[col + 1];
            #pragma unroll
            for (int half = 0; half < 2; half++) {
                const int r = ra + half * 8;
                const float v0 = acc[mf][nf][half * 2 + 0] + b0;
                const float v1 = acc[mf][nf][half * 2 + 1] + b1;
                if (GELU) {
                    const float g0 = 0.5f * v0 * (1.0f + erff(v0 * 0.70710678118654752f));
                    const float g1 = 0.5f * v1 * (1.0f + erff(v1 * 0.70710678118654752f));
                    __nv_bfloat16 h0 = __float2bfloat16(g0);
                    __nv_bfloat16 h1 = __float2bfloat16(g1);
                    __nv_bfloat162 hp; hp.x = h0; hp.y = h1;
                    __nv_bfloat162 lp;
                    lp.x = __float2bfloat16(g0 - __bfloat162float(h0));
                    lp.y = __float2bfloat16(g1 - __bfloat162float(h1));
                    *(__nv_bfloat162*)&Ohi[(size_t)r * N + col] = hp;
                    *(__nv_bfloat162*)&Olo[(size_t)r * N + col] = lp;
                } else {
                    const float2 rr = *(const float2*)&res[(size_t)r * N + col];
                    float2 o = make_float2(v0 + rr.x, v1 + rr.y);
                    *(float2*)&Of[(size_t)r * N + col] = o;
                }
            }
        }
    }
}

// ---------------- launch ----------------------------------------------------
extern "C" void kernel_launch(void* const* d_in, const int* in_sizes, int n_in,
                              void* d_out, int out_size) {
    const float* x   = (const float*)d_in[0];
    const float* w1  = (const float*)d_in[1];
    const float* b1  = (const float*)d_in[2];
    const float* w2  = (const float*)d_in[3];
    const float* b2  = (const float*)d_in[4];
    const float* g1  = (const float*)d_in[5];
    const float* be1 = (const float*)d_in[6];
    const float* g2  = (const float*)d_in[7];
    const float* be2 = (const float*)d_in[8];
    float* out = (float*)d_out;

    float *fr, *fi, *h;
    __nv_bfloat16 *acth, *actl, *w1h, *w1l, *w2h, *w2l;
    cudaGetSymbolAddress((void**)&fr,   g_fr);
    cudaGetSymbolAddress((void**)&fi,   g_fi);
    cudaGetSymbolAddress((void**)&h,    g_h);
    cudaGetSymbolAddress((void**)&acth, g_act_hi);
    cudaGetSymbolAddress((void**)&actl, g_act_lo);
    cudaGetSymbolAddress((void**)&w1h,  g_w1t_hi);
    cudaGetSymbolAddress((void**)&w1l,  g_w1t_lo);
    cudaGetSymbolAddress((void**)&w2h,  g_w2t_hi);
    cudaGetSymbolAddress((void**)&w2l,  g_w2t_lo);

    // h hi/lo split lives in g_fi (dead after LN1 consumes fft imag part;
    // GEMM2 overwrites it only after acth/actl were produced from it)
    __nv_bfloat16* hh = (__nv_bfloat16*)fi;
    __nv_bfloat16* hl = hh + (size_t)TOT;

    cudaFuncSetAttribute(mma_gemm_kernel<0>,
                         cudaFuncAttributeMaxDynamicSharedMemorySize, GEMM_SMEM);
    cudaFuncSetAttribute(mma_gemm_kernel<1>,
                         cudaFuncAttributeMaxDynamicSharedMemorySize, GEMM_SMEM);
    cudaFuncSetAttribute(fft_seq_kernel,
                         cudaFuncAttributeMaxDynamicSharedMemorySize, SEQ_SMEM);

    // 1. twiddles + weight prep
    twiddle_init_kernel<<<8, 256>>>();
    transpose_split_kernel<<<dim3(FF / 32, HID / 32), dim3(32, 8)>>>(w1, w1h, w1l, HID, FF);
    transpose_split_kernel<<<dim3(HID / 32, FF / 32), dim3(32, 8)>>>(w2, w2h, w2l, FF, HID);
    // 2. FFT over hidden dim -> (g_fr, g_fi)
    fft_hidden_kernel<<<NROWS, 256>>>(x);
    // 3. FFT over seq dim (4 columns/block), real part -> g_fr (= x_ft)
    fft_seq_kernel<<<BATCH * HID / 4, 512, SEQ_SMEM>>>();
    // 4. h = LN1(x + x_ft), fused bf16 hi/lo split into g_fi
    add_ln_kernel<<<NROWS, 256>>>(x, fr, g1, be1, h, hh, hl);
    // 5. act(hi/lo bf16) = gelu(h @ w1 + b1)
    mma_gemm_kernel<1><<<dim3(FF / 128, NROWS / 128), 256, GEMM_SMEM>>>(
        hh, hl, w1h, w1l, b1, nullptr, acth, actl, nullptr, NROWS, FF, HID);
    // 6. y = act @ w2 + b2 + h -> g_fi (overwrites dead hh/hl)
    mma_gemm_kernel<0><<<dim3(HID / 128, NROWS / 128), 256, GEMM_SMEM>>>(
        acth, actl, w2h, w2l, b2, h, nullptr, nullptr, fi, NROWS, HID, FF);
    // 7. out = LN2(y)
    add_ln_kernel<<<NROWS, 256>>>(fi, nullptr, g2, be2, out, nullptr, nullptr);
}

// round 15
// speedup vs baseline: 2.9216x; 1.0049x over previous
#include <cuda_runtime.h>
#include <cuda_bf16.h>
#include <math.h>
#include <stdint.h>

#define BATCH 4
#define SEQ   4096
#define HID   1024
#define FF    4096
#define NROWS (BATCH*SEQ)          // 16384
#define TOT   (NROWS*HID)          // 16777216

// ---------------- scratch (static device arrays; no allocation allowed) ----
__device__ float  g_fr[TOT];                 // x_ft
__device__ float  g_fi[TOT];                 // fft imag; then h hi/lo; then y
__device__ float  g_h [TOT];                 // h = LN1(x + x_ft)
__device__ __nv_bfloat16 g_act_hi[(size_t)NROWS*FF];
__device__ __nv_bfloat16 g_act_lo[(size_t)NROWS*FF];
__device__ __nv_bfloat16 g_w1t_hi[(size_t)HID*FF];  // [FF][HID] K-major
__device__ __nv_bfloat16 g_w1t_lo[(size_t)HID*FF];
__device__ __nv_bfloat16 g_w2t_hi[(size_t)HID*FF];  // [HID][FF] K-major
__device__ __nv_bfloat16 g_w2t_lo[(size_t)HID*FF];
__device__ float2 g_tw[2048];                // e^{-2*pi*i*j/4096}

// ============================================================================
// PTX helpers (arch-generic: mma.sync + cp.async + ldmatrix)
// ============================================================================
__device__ __forceinline__ uint32_t smem_u32(const void* p) {
    uint32_t a;
    asm("{ .reg .u64 t; cvta.to.shared.u64 t, %1; cvt.u32.u64 %0, t; }"
        : "=r"(a) : "l"(p));
    return a;
}
__device__ __forceinline__ void mma16816(float* d,
                                         uint32_t a0, uint32_t a1, uint32_t a2, uint32_t a3,
                                         uint32_t b0, uint32_t b1) {
    asm volatile(
        "mma.sync.aligned.m16n8k16.row.col.f32.bf16.bf16.f32 "
        "{%0,%1,%2,%3}, {%4,%5,%6,%7}, {%8,%9}, {%0,%1,%2,%3};"
        : "+f"(d[0]), "+f"(d[1]), "+f"(d[2]), "+f"(d[3])
        : "r"(a0), "r"(a1), "r"(a2), "r"(a3), "r"(b0), "r"(b1));
}
#define LDM_X4(r0, r1, r2, r3, addr) \
    asm volatile("ldmatrix.sync.aligned.m8n8.x4.shared.b16 {%0,%1,%2,%3}, [%4];" \
        : "=r"(r0), "=r"(r1), "=r"(r2), "=r"(r3) : "r"(addr))
#define CP_ASYNC16(dst_u32, src_ptr) \
    asm volatile("cp.async.cg.shared.global [%0], [%1], 16;" \
        :: "r"(dst_u32), "l"(src_ptr))
#define CP_COMMIT() asm volatile("cp.async.commit_group;" ::: "memory")
#define CP_WAIT(n)  asm volatile("cp.async.wait_group %0;" :: "n"(n) : "memory")

__device__ __forceinline__ float2 cmul(float2 a, float2 b) {
    return make_float2(a.x * b.x - a.y * b.y, a.y * b.x + a.x * b.y);
}

// ---------------- twiddle init ---------------------------------------------
__global__ void twiddle_init_kernel() {
    int j = blockIdx.x * blockDim.x + threadIdx.x;
    if (j < 2048) {
        float ang = -6.283185307179586f * (float)j / 4096.0f;
        float s, c;
        sincosf(ang, &s, &c);
        g_tw[j] = make_float2(c, s);
    }
}

// ---------------- weight transpose + hi/lo split ----------------------------
__global__ void transpose_split_kernel(const float* __restrict__ W,
                                       __nv_bfloat16* __restrict__ Thi,
                                       __nv_bfloat16* __restrict__ Tlo,
                                       int K, int N) {
    __shared__ float t[32][33];
    const int n = blockIdx.x * 32 + threadIdx.x;
    const int k0 = blockIdx.y * 32;
    #pragma unroll
    for (int j = 0; j < 32; j += 8)
        t[threadIdx.y + j][threadIdx.x] = W[(size_t)(k0 + threadIdx.y + j) * N + n];
    __syncthreads();
    const int k = k0 + threadIdx.x;
    #pragma unroll
    for (int j = 0; j < 32; j += 8) {
        float v = t[threadIdx.x][threadIdx.y + j];
        __nv_bfloat16 hi = __float2bfloat16(v);
        float lo = v - __bfloat162float(hi);
        size_t o = (size_t)(blockIdx.x * 32 + threadIdx.y + j) * K + k;
        Thi[o] = hi;
        Tlo[o] = __float2bfloat16(lo);
    }
}

// ---------------- FFT over hidden dim (N=1024), radix-4, one row/block -----
// Padded smem index (one extra float2 per 16) -> conflict-free butterflies.
#define PAD16(i) ((i) + ((i) >> 4))
#define HID_SMEM_ELEMS (1024 + 64)
__global__ void fft_hidden_kernel(const float* __restrict__ x) {
    __shared__ float2 sc[HID_SMEM_ELEMS];
    const int row = blockIdx.x;
    const float* xp = x + (size_t)row * HID;
    for (int i = threadIdx.x; i < 1024; i += 256) {
        int r = __brev((unsigned)i) >> 22;
        sc[PAD16(r)] = make_float2(xp[i], 0.f);
    }
    __syncthreads();
    #pragma unroll
    for (int p = 0; p < 5; p++) {
        const int s = 2 * p + 1;
        const int q = 1 << (s - 1);
        const int j = threadIdx.x;                 // 256 butterflies
        const int k  = j & (q - 1);
        const int i0 = ((j >> (s - 1)) << (s + 1)) + k;
        const float2 w1 = g_tw[k << (12 - s)];
        const float2 w2 = g_tw[k << (11 - s)];
        float2 a = sc[PAD16(i0)];
        float2 b = sc[PAD16(i0 + q)];
        float2 c = sc[PAD16(i0 + 2 * q)];
        float2 d = sc[PAD16(i0 + 3 * q)];
        float2 wb = cmul(w1, b), wd = cmul(w1, d);
        float2 A = make_float2(a.x + wb.x, a.y + wb.y);
        float2 B = make_float2(a.x - wb.x, a.y - wb.y);
        float2 C = make_float2(c.x + wd.x, c.y + wd.y);
        float2 D = make_float2(c.x - wd.x, c.y - wd.y);
        float2 wC = cmul(w2, C), wD = cmul(w2, D);
        sc[PAD16(i0)]         = make_float2(A.x + wC.x, A.y + wC.y);
        sc[PAD16(i0 + 2 * q)] = make_float2(A.x - wC.x, A.y - wC.y);
        sc[PAD16(i0 + q)]     = make_float2(B.x + wD.y, B.y - wD.x);  // -i*wD
        sc[PAD16(i0 + 3 * q)] = make_float2(B.x - wD.y, B.y + wD.x);
        __syncthreads();
    }
    float* fr = g_fr + (size_t)row * HID;
    float* fi = g_fi + (size_t)row * HID;
    for (int i = threadIdx.x; i < 1024; i += 256) {
        float2 v = sc[PAD16(i)];
        fr[i] = v.x;
        fi[i] = v.y;
    }
}

// ---------------- FFT over seq dim (N=4096), radix-4, 4 columns/block ------
#define SEQ_COL_ELEMS (4096 + 256)                  // padded column stride
#define SEQ_SMEM (4 * SEQ_COL_ELEMS * (int)sizeof(float2))   // 139264 B
__global__ void fft_seq_kernel() {
    extern __shared__ float2 sc4[];                 // [4][SEQ_COL_ELEMS]
    const int col0 = blockIdx.x * 4;
    const int b    = col0 >> 10;
    const int h0   = col0 & 1023;
    const size_t base = (size_t)b * SEQ * HID + h0;

    for (int i = threadIdx.x; i < 4096; i += 512) {
        int r = PAD16(__brev((unsigned)i) >> 20);
        float4 vr = *(const float4*)(g_fr + base + (size_t)i * HID);
        float4 vi = *(const float4*)(g_fi + base + (size_t)i * HID);
        sc4[0 * SEQ_COL_ELEMS + r] = make_float2(vr.x, vi.x);
        sc4[1 * SEQ_COL_ELEMS + r] = make_float2(vr.y, vi.y);
        sc4[2 * SEQ_COL_ELEMS + r] = make_float2(vr.z, vi.z);
        sc4[3 * SEQ_COL_ELEMS + r] = make_float2(vr.w, vi.w);
    }
    __syncthreads();

    {
        const int c  = threadIdx.x >> 7;            // 0..3, warp-uniform
        const int jb = threadIdx.x & 127;
        float2* cs = sc4 + c * SEQ_COL_ELEMS;
        #pragma unroll
        for (int p = 0; p < 6; p++) {
            const int s = 2 * p + 1;
            const int q = 1 << (s - 1);
            #pragma unroll
            for (int j = jb; j < 1024; j += 128) {  // 1024 butterflies/column
                const int k  = j & (q - 1);
                const int i0 = ((j >> (s - 1)) << (s + 1)) + k;
                const float2 w1 = g_tw[k << (12 - s)];
                const float2 w2 = g_tw[k << (11 - s)];
                float2 a = cs[PAD16(i0)];
                float2 bb = cs[PAD16(i0 + q)];
                float2 cc = cs[PAD16(i0 + 2 * q)];
                float2 d = cs[PAD16(i0 + 3 * q)];
                float2 wb = cmul(w1, bb), wd = cmul(w1, d);
                float2 A = make_float2(a.x + wb.x, a.y + wb.y);
                float2 B = make_float2(a.x - wb.x, a.y - wb.y);
                float2 C = make_float2(cc.x + wd.x, cc.y + wd.y);
                float2 D = make_float2(cc.x - wd.x, cc.y - wd.y);
                float2 wC = cmul(w2, C), wD = cmul(w2, D);
                cs[PAD16(i0)]         = make_float2(A.x + wC.x, A.y + wC.y);
                cs[PAD16(i0 + 2 * q)] = make_float2(A.x - wC.x, A.y - wC.y);
                cs[PAD16(i0 + q)]     = make_float2(B.x + wD.y, B.y - wD.x);
                cs[PAD16(i0 + 3 * q)] = make_float2(B.x - wD.y, B.y + wD.x);
            }
            __syncthreads();
        }
    }

    for (int i = threadIdx.x; i < 4096; i += 512) {
        int si = PAD16(i);
        float4 o = make_float4(sc4[0 * SEQ_COL_ELEMS + si].x,
                               sc4[1 * SEQ_COL_ELEMS + si].x,
                               sc4[2 * SEQ_COL_ELEMS + si].x,
                               sc4[3 * SEQ_COL_ELEMS + si].x);
        *(float4*)(g_fr + base + (size_t)i * HID) = o;   // real part only
    }
}

// ---------------- out = LayerNorm(a [+ b]); optional bf16 hi/lo split ------
__global__ void add_ln_kernel(const float* __restrict__ a,
                              const float* __restrict__ badd,
                              const float* __restrict__ gamma,
                              const float* __restrict__ beta,
                              float* __restrict__ out,
                              __nv_bfloat16* __restrict__ ohi,
                              __nv_bfloat16* __restrict__ olo) {
    const int row = blockIdx.x;
    const int tid = threadIdx.x;
    const float4* a4 = (const float4*)(a + (size_t)row * HID);
    float4 v = a4[tid];
    if (badd) {
        const float4* b4 = (const float4*)(badd + (size_t)row * HID);
        float4 w = b4[tid];
        v.x += w.x; v.y += w.y; v.z += w.z; v.w += w.w;
    }
    float sum = v.x + v.y + v.z + v.w;
    float sq  = v.x*v.x + v.y*v.y + v.z*v.z + v.w*v.w;
    __shared__ float s1[8], s2[8];
    #pragma unroll
    for (int o = 16; o > 0; o >>= 1) {
        sum += __shfl_xor_sync(0xffffffffu, sum, o);
        sq  += __shfl_xor_sync(0xffffffffu, sq,  o);
    }
    const int warp = tid >> 5, lane = tid & 31;
    if (lane == 0) { s1[warp] = sum; s2[warp] = sq; }
    __syncthreads();
    if (warp == 0) {
        float a1 = (lane < 8) ? s1[lane] : 0.f;
        float a2 = (lane < 8) ? s2[lane] : 0.f;
        #pragma unroll
        for (int o = 4; o > 0; o >>= 1) {
            a1 += __shfl_xor_sync(0xffffffffu, a1, o);
            a2 += __shfl_xor_sync(0xffffffffu, a2, o);
        }
        if (lane == 0) { s1[0] = a1; s2[0] = a2; }
    }
    __syncthreads();
    const float mu  = s1[0] * (1.0f / 1024.0f);
    const float var = s2[0] * (1.0f / 1024.0f) - mu * mu;
    const float inv = rsqrtf(var + 1e-5f);
    const float4 g  = ((const float4*)gamma)[tid];
    const float4 bt = ((const float4*)beta)[tid];
    float o[4];
    o[0] = (v.x - mu) * inv * g.x + bt.x;
    o[1] = (v.y - mu) * inv * g.y + bt.y;
    o[2] = (v.z - mu) * inv * g.z + bt.z;
    o[3] = (v.w - mu) * inv * g.w + bt.w;
    ((float4*)(out + (size_t)row * HID))[tid] = *(float4*)o;
    if (ohi) {
        __nv_bfloat16 h[4], l[4];
        #pragma unroll
        for (int e = 0; e < 4; e++) {
            h[e] = __float2bfloat16(o[e]);
            l[e] = __float2bfloat16(o[e] - __bfloat162float(h[e]));
        }
        const size_t off = (size_t)row * HID + tid * 4;
        *(uint2*)(ohi + off) = *(uint2*)h;
        *(uint2*)(olo + off) = *(uint2*)l;
    }
}

// ============================================================================
// bf16 split GEMM on mma.sync.m16n8k16.  CTA tile 128x128, BK=32, 8 warps,
// warp tile 64x32.  2-stage cp.async pipeline, ONE barrier per chunk,
// 2 CTAs/SM (80KB smem each) for cross-CTA latency hiding.
// 3 split terms: Ahi*Bhi + Ahi*Blo + Alo*Bhi into fp32 accumulators.
// GELU=1: C = gelu(A@B + bias) -> bf16 hi/lo.   GELU=0: C = A@B+bias+res (f32)
// ============================================================================
#define LDK 40                      // padded row stride (bf16 elems), 80 bytes
#define BUF_BYTES (128 * LDK * 2)   // 10240 B
#define STAGES 2
#define GEMM_SMEM (STAGES * 4 * BUF_BYTES)   // 81920 B

template<int GELU>
__global__ void __launch_bounds__(256, 2)
mma_gemm_kernel(const __nv_bfloat16* __restrict__ Ahi,
                const __nv_bfloat16* __restrict__ Alo,
                const __nv_bfloat16* __restrict__ Bhi,
                const __nv_bfloat16* __restrict__ Blo,
                const float* __restrict__ bias,
                const float* __restrict__ res,
                __nv_bfloat16* __restrict__ Ohi,
                __nv_bfloat16* __restrict__ Olo,
                float* __restrict__ Of,
                int M, int N, int K)
{
    extern __shared__ __nv_bfloat16 smem[];   // [STAGES][4 bufs][128][LDK]
    const int tid  = threadIdx.x;
    const int wid  = tid >> 5;
    const int lane = tid & 31;
    const int wm = wid >> 2;        // 0..1
    const int wn = wid & 3;         // 0..3
    const int g  = lane >> 2;       // 0..7
    const int tg = lane & 3;        // 0..3
    const int m0 = blockIdx.y * 128;
    const int n0 = blockIdx.x * 128;

    // cp.async mapping: 16B per thread per 64-row half per buffer
    const int r0c = tid >> 2;              // rows 0..63
    const int kc0 = (tid & 3) * 8;         // bf16 elem offset within BK=32
    const uint32_t sbase = smem_u32(smem);

    // ldmatrix A addresses: x4 -> rows g/g+8 x cols 0/8
    const int arow = wm * 64 + (lane & 7) + ((lane >> 3) & 1) * 8;  // +mf*16
    const int acol = (lane >> 4) * 8;                               // +ks*16
    const uint32_t aoff = (uint32_t)(arow * LDK + acol) * 2;
    // ldmatrix B addresses: x4 covering nf-pair
    const int brow = wn * 32 + (lane & 7) + ((lane >> 4) & 1) * 8;  // +pair*16
    const int bcol = ((lane >> 3) & 1) * 8;                         // +ks*16
    const uint32_t boff = (uint32_t)(brow * LDK + bcol) * 2;

    const __nv_bfloat16* srcA[2] = {Ahi, Alo};
    const __nv_bfloat16* srcB[2] = {Bhi, Blo};

    float acc[4][4][4];
    #pragma unroll
    for (int i = 0; i < 4; i++)
        #pragma unroll
        for (int j = 0; j < 4; j++)
            #pragma unroll
            for (int e = 0; e < 4; e++) acc[i][j][e] = 0.f;

    const int NC = K >> 5;          // K / 32

    // Always commits exactly one group (empty if cidx >= NC).
    #define PREFETCH(cidx, stage) do {                                         \
        if ((cidx) < NC) {                                                     \
            const int _k0 = (cidx) << 5;                                       \
            uint32_t _sb = sbase + (stage) * 4 * BUF_BYTES;                    \
            _Pragma("unroll")                                                  \
            for (int _h = 0; _h < 2; _h++) {                                   \
                _Pragma("unroll")                                              \
                for (int _half = 0; _half < 2; _half++) {                      \
                    int _row = r0c + _half * 64;                               \
                    uint32_t _d = _sb + (_h) * BUF_BYTES +                     \
                                  (_row * LDK + kc0) * 2;                      \
                    CP_ASYNC16(_d, srcA[_h] + (size_t)(m0 + _row) * K + _k0 + kc0);  \
                    uint32_t _d2 = _sb + (2 + _h) * BUF_BYTES +                \
                                   (_row * LDK + kc0) * 2;                     \
                    CP_ASYNC16(_d2, srcB[_h] + (size_t)(n0 + _row) * K + _k0 + kc0); \
                }                                                              \
            }                                                                  \
        }                                                                      \
        CP_COMMIT();                                                           \
    } while (0)

    PREFETCH(0, 0);

    for (int c = 0; c < NC; c++) {
        const int st = c & 1;
        CP_WAIT(0);
        __syncthreads();
        // stage st^1's last readers finished chunk c-1 before this barrier
        PREFETCH(c + 1, st ^ 1);

        const uint32_t sAh = sbase + (st * 4 + 0) * BUF_BYTES;
        const uint32_t sAl = sbase + (st * 4 + 1) * BUF_BYTES;
        const uint32_t sBh = sbase + (st * 4 + 2) * BUF_BYTES;
        const uint32_t sBl = sbase + (st * 4 + 3) * BUF_BYTES;

        #pragma unroll
        for (int ks = 0; ks < 2; ks++) {
            uint32_t bh[4][2], bl[4][2];
            #pragma unroll
            for (int pr = 0; pr < 2; pr++) {       // nf pairs {0,1}, {2,3}
                const uint32_t bo = boff + pr * (16 * LDK * 2) + ks * 32;
                LDM_X4(bh[pr*2][0], bh[pr*2][1], bh[pr*2+1][0], bh[pr*2+1][1], sBh + bo);
                LDM_X4(bl[pr*2][0], bl[pr*2][1], bl[pr*2+1][0], bl[pr*2+1][1], sBl + bo);
            }
            #pragma unroll
            for (int mf = 0; mf < 4; mf++) {
                uint32_t ah[4], al[4];
                const uint32_t ao = aoff + mf * (16 * LDK * 2) + ks * 32;
                LDM_X4(ah[0], ah[1], ah[2], ah[3], sAh + ao);
                LDM_X4(al[0], al[1], al[2], al[3], sAl + ao);
                #pragma unroll
                for (int nf = 0; nf < 4; nf++) {
                    mma16816(acc[mf][nf], ah[0], ah[1], ah[2], ah[3],
                             bh[nf][0], bh[nf][1]);
                    mma16816(acc[mf][nf], ah[0], ah[1], ah[2], ah[3],
                             bl[nf][0], bl[nf][1]);
                    mma16816(acc[mf][nf], al[0], al[1], al[2], al[3],
                             bh[nf][0], bh[nf][1]);
                }
            }
        }
    }
    #undef PREFETCH

    // ---- epilogue ----
    #pragma unroll
    for (int mf = 0; mf < 4; mf++) {
        const int ra = m0 + wm * 64 + mf * 16 + g;
        #pragma unroll
        for (int nf = 0; nf < 4; nf++) {
            const int col = n0 + wn * 32 + nf * 8 + tg * 2;
            const float b0 = bias[col], b1 = bias[col + 1];
            #pragma unroll
            for (int half = 0; half < 2; half++) {
                const int r = ra + half * 8;
                const float v0 = acc[mf][nf][half * 2 + 0] + b0;
                const float v1 = acc[mf][nf][half * 2 + 1] + b1;
                if (GELU) {
                    const float g0 = 0.5f * v0 * (1.0f + erff(v0 * 0.70710678118654752f));
                    const float g1 = 0.5f * v1 * (1.0f + erff(v1 * 0.70710678118654752f));
                    __nv_bfloat16 h0 = __float2bfloat16(g0);
                    __nv_bfloat16 h1 = __float2bfloat16(g1);
                    __nv_bfloat162 hp; hp.x = h0; hp.y = h1;
                    __nv_bfloat162 lp;
                    lp.x = __float2bfloat16(g0 - __bfloat162float(h0));
                    lp.y = __float2bfloat16(g1 - __bfloat162float(h1));
                    *(__nv_bfloat162*)&Ohi[(size_t)r * N + col] = hp;
                    *(__nv_bfloat162*)&Olo[(size_t)r * N + col] = lp;
                } else {
                    const float2 rr = *(const float2*)&res[(size_t)r * N + col];
                    float2 o = make_float2(v0 + rr.x, v1 + rr.y);
                    *(float2*)&Of[(size_t)r * N + col] = o;
                }
            }
        }
    }
}

// ---------------- launch ----------------------------------------------------
extern "C" void kernel_launch(void* const* d_in, const int* in_sizes, int n_in,
                              void* d_out, int out_size) {
    const float* x   = (const float*)d_in[0];
    const float* w1  = (const float*)d_in[1];
    const float* b1  = (const float*)d_in[2];
    const float* w2  = (const float*)d_in[3];
    const float* b2  = (const float*)d_in[4];
    const float* g1  = (const float*)d_in[5];
    const float* be1 = (const float*)d_in[6];
    const float* g2  = (const float*)d_in[7];
    const float* be2 = (const float*)d_in[8];
    float* out = (float*)d_out;

    float *fr, *fi, *h;
    __nv_bfloat16 *acth, *actl, *w1h, *w1l, *w2h, *w2l;
    cudaGetSymbolAddress((void**)&fr,   g_fr);
    cudaGetSymbolAddress((void**)&fi,   g_fi);
    cudaGetSymbolAddress((void**)&h,    g_h);
    cudaGetSymbolAddress((void**)&acth, g_act_hi);
    cudaGetSymbolAddress((void**)&actl, g_act_lo);
    cudaGetSymbolAddress((void**)&w1h,  g_w1t_hi);
    cudaGetSymbolAddress((void**)&w1l,  g_w1t_lo);
    cudaGetSymbolAddress((void**)&w2h,  g_w2t_hi);
    cudaGetSymbolAddress((void**)&w2l,  g_w2t_lo);

    // h hi/lo split lives in g_fi (dead after LN1 consumes fft imag part;
    // GEMM2 overwrites it only after acth/actl were produced from it)
    __nv_bfloat16* hh = (__nv_bfloat16*)fi;
    __nv_bfloat16* hl = hh + (size_t)TOT;

    cudaFuncSetAttribute(mma_gemm_kernel<0>,
                         cudaFuncAttributeMaxDynamicSharedMemorySize, GEMM_SMEM);
    cudaFuncSetAttribute(mma_gemm_kernel<1>,
                         cudaFuncAttributeMaxDynamicSharedMemorySize, GEMM_SMEM);
    cudaFuncSetAttribute(fft_seq_kernel,
                         cudaFuncAttributeMaxDynamicSharedMemorySize, SEQ_SMEM);

    // 1. twiddles + weight prep
    twiddle_init_kernel<<<8, 256>>>();
    transpose_split_kernel<<<dim3(FF / 32, HID / 32), dim3(32, 8)>>>(w1, w1h, w1l, HID, FF);
    transpose_split_kernel<<<dim3(HID / 32, FF / 32), dim3(32, 8)>>>(w2, w2h, w2l, FF, HID);
    // 2. FFT over hidden dim -> (g_fr, g_fi)
    fft_hidden_kernel<<<NROWS, 256>>>(x);
    // 3. FFT over seq dim (4 columns/block), real part -> g_fr (= x_ft)
    fft_seq_kernel<<<BATCH * HID / 4, 512, SEQ_SMEM>>>();
    // 4. h = LN1(x + x_ft), fused bf16 hi/lo split into g_fi
    add_ln_kernel<<<NROWS, 256>>>(x, fr, g1, be1, h, hh, hl);
    // 5. act(hi/lo bf16) = gelu(h @ w1 + b1)
    mma_gemm_kernel<1><<<dim3(FF / 128, NROWS / 128), 256, GEMM_SMEM>>>(
        hh, hl, w1h, w1l, b1, nullptr, acth, actl, nullptr, NROWS, FF, HID);
    // 6. y = act @ w2 + b2 + h -> g_fi (overwrites dead hh/hl)
    mma_gemm_kernel<0><<<dim3(HID / 128, NROWS / 128), 256, GEMM_SMEM>>>(
        acth, actl, w2h, w2l, b2, h, nullptr, nullptr, fi, NROWS, HID, FF);
    // 7. out = LN2(y)
    add_ln_kernel<<<NROWS, 256>>>(fi, nullptr, g2, be2, out, nullptr, nullptr);
}